// round 5
// baseline (speedup 1.0000x reference)
#include <cuda_runtime.h>
#include <math.h>

#define BB 64
#define TT 26
#define EE 300
#define HH 1024
#define G4 4096
#define FEATN 2048
#define SS 49
#define D1N 245000
#define D2N 5000
#define MON 1000
#define VOCABN 3000
#define QDIM 2048
#define IDIM 4096
#define IQN (MON*SS)

// conv1 tiling: 20 bins, 40-m tiles -> 2 blocks/SM
#define BIN1 12250
#define NBINS 20
#define MTILE 40
#define CTHREADS 640
// max smem index: (BIN1-1) + (245*9+63) + 2450*3 = 21867
#define WSZ 21872
#define CONV_SMEM (WSZ*4 + QDIM*4 + QDIM*4)

// ---------------- scratch (device globals) ----------------
__device__ float g_xW[TT*BB*G4];
__device__ float g_c[BB*HH];
__device__ float g_hs[TT*BB*HH];
__device__ float g_qa1[TT*BB*512];
__device__ float g_qa2[BB*2*TT];
__device__ float g_qatt[BB*2*TT];
__device__ float g_qfeat[BB*QDIM];
__device__ float g_qv1[BB*QDIM];
__device__ float g_qv2[BB*QDIM];
__device__ float g_qp1[BB*QDIM];
__device__ float g_csx[BB*D1N];
__device__ float g_P1[BB*D1N];
__device__ float g_iq[BB*IQN];
__device__ float g_nrm1[BB];
__device__ float g_iqn[BB*IQN];
__device__ float g_ia1[BB*SS*512];
__device__ float g_ia2[BB*2*SS];
__device__ float g_iatt[BB*2*SS];
__device__ float g_ifeat[BB*IDIM];
__device__ float g_z2n[BB*MON];
__device__ float g_logits[BB*VOCABN];
__device__ int   g_binoff[NBINS+1];
__device__ int   g_perm[QDIM];
__device__ int   g_hperm[QDIM];

__device__ __forceinline__ float sigmoidf_(float x) { return 1.f / (1.f + expf(-x)); }

// packed f32x2 helpers
#define PK2(d_, lo_, hi_) asm("mov.b64 %0, {%1, %2};" : "=l"(d_) : "f"(lo_), "f"(hi_))
#define FMA2(a_, b_, c_)  asm("fma.rn.f32x2 %0, %1, %2, %0;" : "+l"(c_) : "l"(a_), "l"(b_))
__device__ __forceinline__ float upk_sum(unsigned long long v) {
    float lo, hi;
    asm("mov.b64 {%0, %1}, %2;" : "=f"(lo), "=f"(hi) : "l"(v));
    return lo + hi;
}

// ---------------- init ----------------
__global__ void init_state_k() {
    int i = blockIdx.x * 256 + threadIdx.x;
    if (i < BB * HH) g_c[i] = 0.f;
}
__global__ void zero_csx_k() {
    int i = blockIdx.x * 256 + threadIdx.x;
    if (i < BB * D1N) g_csx[i] = 0.f;
}

// ---------------- bin h1q ----------------
__global__ void bin_h_k(const int* __restrict__ h1q) {
    __shared__ int cnt[NBINS];
    __shared__ int ofs[NBINS];
    int tid = threadIdx.x;
    if (tid < NBINS) cnt[tid] = 0;
    __syncthreads();
    for (int j = tid; j < QDIM; j += 256) atomicAdd(&cnt[h1q[j] / BIN1], 1);
    __syncthreads();
    if (tid == 0) {
        int s = 0;
        for (int k = 0; k < NBINS; k++) { g_binoff[k] = s; ofs[k] = s; s += cnt[k]; }
        g_binoff[NBINS] = s;
    }
    __syncthreads();
    for (int j = tid; j < QDIM; j += 256) {
        int h = h1q[j];
        int p = atomicAdd(&ofs[h / BIN1], 1);
        g_perm[p] = j;
        g_hperm[p] = h;
    }
}

__global__ void permq_k() {
    int b = blockIdx.x;
    for (int i = threadIdx.x; i < QDIM; i += 256)
        g_qp1[b * QDIM + i] = g_qv1[b * QDIM + g_perm[i]];
}

// ---------------- generic tiled SGEMM ----------------
__global__ void sgemm(const float* __restrict__ A, const float* __restrict__ W,
                      const float* __restrict__ bias1, const float* __restrict__ bias2,
                      float* __restrict__ C,
                      int M, int N, int K, int RD, int S1, int S2, int kstride, int relu)
{
    __shared__ float As[16][64];
    __shared__ float Bs[16][64];
    const int bn = blockIdx.x * 64;
    const int bm = blockIdx.y * 64;
    const int tid = threadIdx.x;
    const int tm = (tid / 16) * 4;
    const int tn = (tid % 16) * 4;

    int kPer = (K + gridDim.z - 1) / gridDim.z;
    int kBeg = blockIdx.z * kPer;
    int kEnd = min(K, kBeg + kPer);

    float acc[4][4];
#pragma unroll
    for (int i = 0; i < 4; i++)
#pragma unroll
        for (int j = 0; j < 4; j++) acc[i][j] = 0.f;

    const int lm = tid >> 2;
    const int lk = (tid & 3) << 2;

    for (int k0 = kBeg; k0 < kEnd; k0 += 16) {
        {
            int row = bm + lm;
            float va[4] = {0.f, 0.f, 0.f, 0.f};
            if (row < M) {
                size_t base = (size_t)(row / RD) * S1 + (size_t)(row % RD) * S2;
                int kg = k0 + lk;
#pragma unroll
                for (int i = 0; i < 4; i++)
                    if (kg + i < kEnd) va[i] = A[base + (size_t)(kg + i) * kstride];
            }
#pragma unroll
            for (int i = 0; i < 4; i++) As[lk + i][lm] = va[i];
        }
        {
            int col = bn + lm;
            float vb[4] = {0.f, 0.f, 0.f, 0.f};
            if (col < N) {
                int kg = k0 + lk;
#pragma unroll
                for (int i = 0; i < 4; i++)
                    if (kg + i < kEnd) vb[i] = W[(size_t)col * K + kg + i];
            }
#pragma unroll
            for (int i = 0; i < 4; i++) Bs[lk + i][lm] = vb[i];
        }
        __syncthreads();
#pragma unroll
        for (int k = 0; k < 16; k++) {
            float4 av = *(const float4*)&As[k][tm];
            float4 bv = *(const float4*)&Bs[k][tn];
            float a4[4] = {av.x, av.y, av.z, av.w};
            float b4[4] = {bv.x, bv.y, bv.z, bv.w};
#pragma unroll
            for (int i = 0; i < 4; i++)
#pragma unroll
                for (int j = 0; j < 4; j++) acc[i][j] += a4[i] * b4[j];
        }
        __syncthreads();
    }

    float* Cz = C + (size_t)blockIdx.z * M * N;
#pragma unroll
    for (int i = 0; i < 4; i++) {
        int row = bm + tm + i;
        if (row >= M) continue;
#pragma unroll
        for (int j = 0; j < 4; j++) {
            int col = bn + tn + j;
            if (col >= N) continue;
            float v = acc[i][j];
            if (blockIdx.z == 0) {
                if (bias1) v += bias1[col];
                if (bias2) v += bias2[col];
            }
            if (relu) v = fmaxf(v, 0.f);
            Cz[(size_t)row * N + col] = v;
        }
    }
}

// ---------------- fused LSTM step ----------------
// grid 128 blocks, 256 threads. Block owns 8 h-units (all 4 gates each).
// Reads h from g_hs[t-1], writes h to g_hs[t]; c is block-private in gmem.
#define LSP 33
__global__ __launch_bounds__(256) void lstm_step(const float* __restrict__ W_hh, int t) {
    __shared__ float sh[64 * LSP];
    __shared__ float sw[32 * LSP];
    int tid = threadIdx.x;
    int bgrp = tid & 31;      // 0..31
    int rgrp = tid >> 5;      // 0..7
    int b0 = bgrp * 2;
    int hi = blockIdx.x * 8 + rgrp;

    unsigned long long acc[2][4];
#pragma unroll
    for (int i = 0; i < 2; i++)
#pragma unroll
        for (int g = 0; g < 4; g++) acc[i][g] = 0ull;

    if (t > 0) {
        const float* hprev = g_hs + (size_t)(t - 1) * BB * HH;
        for (int k0 = 0; k0 < HH; k0 += 32) {
            // h tile: 64 x 32
            for (int i = tid; i < 64 * 32; i += 256) {
                int bb = i >> 5, kk = i & 31;
                sh[bb * LSP + kk] = hprev[bb * HH + k0 + kk];
            }
            // w tile: rows rr = hl*4 + g -> W row g*1024 + blk*8 + hl
            for (int i = tid; i < 32 * 32; i += 256) {
                int rr = i >> 5, kk = i & 31;
                int g = rr & 3, hl = rr >> 2;
                sw[rr * LSP + kk] = W_hh[(size_t)(g * HH + blockIdx.x * 8 + hl) * HH + k0 + kk];
            }
            __syncthreads();
#pragma unroll 4
            for (int kk = 0; kk < 32; kk += 2) {
                unsigned long long w2[4];
#pragma unroll
                for (int g = 0; g < 4; g++) {
                    float wl = sw[(rgrp * 4 + g) * LSP + kk];
                    float wh = sw[(rgrp * 4 + g) * LSP + kk + 1];
                    PK2(w2[g], wl, wh);
                }
#pragma unroll
                for (int i = 0; i < 2; i++) {
                    float hl = sh[(b0 + i) * LSP + kk];
                    float hh = sh[(b0 + i) * LSP + kk + 1];
                    unsigned long long h2;
                    PK2(h2, hl, hh);
#pragma unroll
                    for (int g = 0; g < 4; g++) FMA2(h2, w2[g], acc[i][g]);
                }
            }
            __syncthreads();
        }
    }

    // epilogue: gates + state update
#pragma unroll
    for (int i = 0; i < 2; i++) {
        int b = b0 + i;
        const float* xw = g_xW + (size_t)(t * BB + b) * G4;
        float gi = upk_sum(acc[i][0]) + xw[hi];
        float gf = upk_sum(acc[i][1]) + xw[1024 + hi];
        float gg = upk_sum(acc[i][2]) + xw[2048 + hi];
        float go = upk_sum(acc[i][3]) + xw[3072 + hi];
        int id = b * HH + hi;
        float cn = sigmoidf_(gf) * g_c[id] + sigmoidf_(gi) * tanhf(gg);
        float hn = sigmoidf_(go) * tanhf(cn);
        g_c[id] = cn;
        g_hs[(size_t)t * BB * HH + id] = hn;
    }
}

// ---------------- 2-channel 1x1 conv (512 -> 2) ----------------
__global__ void att2_k(const float* __restrict__ X, const float* __restrict__ W2,
                       const float* __restrict__ b2, float* __restrict__ out,
                       int L, int bdiv) {
    int r = blockIdx.x;
    const float* a = X + (size_t)r * 512;
    float s0 = 0.f, s1 = 0.f;
    for (int o = threadIdx.x; o < 512; o += 128) {
        float v = a[o];
        s0 += W2[o] * v; s1 += W2[512 + o] * v;
    }
    __shared__ float r0[128], r1[128];
    r0[threadIdx.x] = s0; r1[threadIdx.x] = s1; __syncthreads();
    for (int st = 64; st > 0; st >>= 1) {
        if (threadIdx.x < st) { r0[threadIdx.x] += r0[threadIdx.x + st]; r1[threadIdx.x] += r1[threadIdx.x + st]; }
        __syncthreads();
    }
    if (threadIdx.x == 0) {
        int b, l;
        if (bdiv == 0) { b = r & 63; l = r >> 6; }
        else { b = r / 49; l = r % 49; }
        out[(b * 2 + 0) * L + l] = r0[0] + b2[0];
        out[(b * 2 + 1) * L + l] = r1[0] + b2[1];
    }
}

// ---------------- small row softmax (n <= 64), 64 threads ----------------
__global__ void softmax_small(const float* __restrict__ in, float* __restrict__ out, int n) {
    __shared__ float sm[64];
    int r = blockIdx.x, tid = threadIdx.x;
    float v = (tid < n) ? in[(size_t)r * n + tid] : -1e30f;
    sm[tid] = v; __syncthreads();
    for (int st = 32; st > 0; st >>= 1) {
        if (tid < st) sm[tid] = fmaxf(sm[tid], sm[tid + st]);
        __syncthreads();
    }
    float mx = sm[0]; __syncthreads();
    float e = (tid < n) ? expf(v - mx) : 0.f;
    sm[tid] = e; __syncthreads();
    for (int st = 32; st > 0; st >>= 1) {
        if (tid < st) sm[tid] += sm[tid + st];
        __syncthreads();
    }
    if (tid < n) out[(size_t)r * n + tid] = e / sm[0];
}

// ---------------- question feature + signed copies ----------------
__global__ void qfeat_k(const int* __restrict__ s1q, const int* __restrict__ s2q) {
    int b = blockIdx.x, g = blockIdx.y;
    __shared__ float att[TT];
    if (threadIdx.x < TT) att[threadIdx.x] = g_qatt[(b * 2 + g) * TT + threadIdx.x];
    __syncthreads();
    for (int h = threadIdx.x; h < HH; h += blockDim.x) {
        float acc = 0.f;
        for (int t = 0; t < TT; t++)
            acc += att[t] * g_hs[((size_t)t * BB + b) * HH + h];
        int j = g * HH + h;
        g_qfeat[b * QDIM + j] = acc;
        g_qv1[b * QDIM + j] = acc * (float)(2 * s1q[j] - 1);
        g_qv2[b * QDIM + j] = acc * (float)(2 * s2q[j] - 1);
    }
}

// ---------------- MCB1: scatter, pool ----------------
__global__ void scatter1(const float* __restrict__ img, const int* __restrict__ h1x,
                         const int* __restrict__ s1x) {
    int id = blockIdx.x * 256 + threadIdx.x;
    if (id >= BB * SS * FEATN) return;
    int f = id % FEATN;
    int r = id / FEATN;
    int s = r % SS, b = r / SS;
    int n = f * SS + s;
    float v = img[id] * (float)(2 * s1x[n] - 1);
    atomicAdd(&g_csx[(size_t)b * D1N + h1x[n]], v);
}

__global__ void pool1() {
    int id = blockIdx.x * 256 + threadIdx.x;
    if (id >= BB * D1N) return;
    int t = id % D1N; int b = id / D1N;
    const float* cs = g_csx + (size_t)b * D1N;
    float a = 0.f;
#pragma unroll
    for (int f = 0; f < 5; f++) {
        int tt = t + 49 * f;
        if (tt >= D1N) tt -= D1N;
        a += cs[tt];
    }
    g_P1[id] = a;
}

// ---------------- MCB1 conv: smem window over bins ----------------
__global__ void conv1_k() {
    extern __shared__ float smw[];
    float* win = smw;                    // [WSZ]
    float* sq  = smw + WSZ;              // [QDIM]
    int*   sh  = (int*)(sq + QDIM);      // [QDIM]
    int b = blockIdx.y;
    int m0 = blockIdx.x * MTILE;
    int tid = threadIdx.x;

    for (int i = tid; i < QDIM; i += CTHREADS) {
        sq[i] = g_qp1[b * QDIM + i];
        sh[i] = g_hperm[i];
    }

    int mg = tid >> 6;
    int sl = tid & 63;
    bool lane_ok = sl < 49;
    int offb = 245 * mg + sl;
    float acc[4] = {0.f, 0.f, 0.f, 0.f};
    const float* Pb = g_P1 + (size_t)b * D1N;
    int T0 = 245 * m0;

    for (int k = 0; k < NBINS; k++) {
        __syncthreads();
        int W0 = T0 - (k + 1) * BIN1 + 1;
        W0 %= D1N; if (W0 < 0) W0 += D1N;
        for (int i = tid; i < WSZ; i += CTHREADS) {
            int g = W0 + i; if (g >= D1N) g -= D1N;
            win[i] = Pb[g];
        }
        __syncthreads();
        int j0 = g_binoff[k], j1 = g_binoff[k + 1];
        if (lane_ok) {
            int base0 = (k + 1) * BIN1 - 1 + offb;
            for (int j = j0; j < j1; j++) {
                float q = sq[j];
                int a = base0 - sh[j];
#pragma unroll
                for (int it = 0; it < 4; it++)
                    acc[it] += q * win[a + 2450 * it];
            }
        }
    }

    if (lane_ok) {
#pragma unroll
        for (int it = 0; it < 4; it++) {
            int m = mg + 10 * it;
            g_iq[(size_t)b * IQN + (m0 + m) * 49 + sl] = acc[it];
        }
    }
}

__global__ void norm1_k() {
    int b = blockIdx.x, tid = threadIdx.x;
    __shared__ float red[256];
    float s = 0.f;
    const float* x = g_iq + (size_t)b * IQN;
    for (int i = tid; i < IQN; i += 256) s += fabsf(x[i]);
    red[tid] = s; __syncthreads();
    for (int st = 128; st > 0; st >>= 1) {
        if (tid < st) red[tid] += red[tid + st];
        __syncthreads();
    }
    if (tid == 0) g_nrm1[b] = 1.f / fmaxf(sqrtf(red[0]), 1e-12f);
}

__global__ void scale1_k() {
    int id = blockIdx.x * 256 + threadIdx.x;
    if (id >= BB * IQN) return;
    int b = id / IQN;
    float x = g_iq[id];
    g_iqn[id] = copysignf(sqrtf(fabsf(x)), x) * g_nrm1[b];
}

// ---------------- image feature ----------------
__global__ void ifeat_k(const float* __restrict__ img) {
    int b = blockIdx.x;
    __shared__ float a0[SS], a1[SS];
    if (threadIdx.x < SS) {
        a0[threadIdx.x] = g_iatt[(b * 2 + 0) * SS + threadIdx.x];
        a1[threadIdx.x] = g_iatt[(b * 2 + 1) * SS + threadIdx.x];
    }
    __syncthreads();
    int f = blockIdx.y * 256 + threadIdx.x;
    float acc0 = 0.f, acc1 = 0.f;
    for (int s = 0; s < SS; s++) {
        float v = img[((size_t)b * SS + s) * FEATN + f];
        acc0 += a0[s] * v; acc1 += a1[s] * v;
    }
    g_ifeat[b * IDIM + f] = acc0;
    g_ifeat[b * IDIM + FEATN + f] = acc1;
}

// ---------------- MCB2 fully fused ----------------
__global__ void mcb2_k(const int* __restrict__ h2i, const int* __restrict__ s2i,
                       const int* __restrict__ h2q) {
    __shared__ float cs[D2N];
    __shared__ float sq[QDIM];
    __shared__ int   shh[QDIM];
    __shared__ float red[256];
    int b = blockIdx.x, tid = threadIdx.x;
    for (int i = tid; i < D2N; i += 256) cs[i] = 0.f;
    for (int j = tid; j < QDIM; j += 256) { sq[j] = g_qv2[b * QDIM + j]; shh[j] = h2q[j]; }
    __syncthreads();
    for (int n = tid; n < IDIM; n += 256) {
        float v = g_ifeat[b * IDIM + n] * (float)(2 * s2i[n] - 1);
        atomicAdd(&cs[h2i[n]], v);
    }
    __syncthreads();
    float p[20];
#pragma unroll
    for (int k = 0; k < 20; k++) {
        int t = tid + k * 256;
        float a = 0.f;
        if (t < D2N) {
#pragma unroll
            for (int f = 0; f < 5; f++) { int u = t + f; if (u >= D2N) u -= D2N; a += cs[u]; }
        }
        p[k] = a;
    }
    __syncthreads();
#pragma unroll
    for (int k = 0; k < 20; k++) { int t = tid + k * 256; if (t < D2N) cs[t] = p[k]; }
    __syncthreads();
    float z[4] = {0.f, 0.f, 0.f, 0.f};
    int mb[4];
#pragma unroll
    for (int k = 0; k < 4; k++) { int m = tid + k * 256; mb[k] = (m < MON) ? 5 * m : 0; }
    for (int j = 0; j < QDIM; j++) {
        int h = shh[j]; float q = sq[j];
#pragma unroll
        for (int k = 0; k < 4; k++) { int d = mb[k] - h; if (d < 0) d += D2N; z[k] += q * cs[d]; }
    }
    float sa = 0.f;
#pragma unroll
    for (int k = 0; k < 4; k++) { if (tid + k * 256 < MON) sa += fabsf(z[k]); }
    red[tid] = sa; __syncthreads();
    for (int st = 128; st > 0; st >>= 1) {
        if (tid < st) red[tid] += red[tid + st];
        __syncthreads();
    }
    float inv = 1.f / fmaxf(sqrtf(red[0]), 1e-12f);
#pragma unroll
    for (int k = 0; k < 4; k++) {
        int m = tid + k * 256;
        if (m < MON) g_z2n[b * MON + m] = copysignf(sqrtf(fabsf(z[k])), z[k]) * inv;
    }
}

// ---------------- final softmax (3000) ----------------
__global__ void softmax_out(float* __restrict__ out) {
    int b = blockIdx.x, tid = threadIdx.x;
    __shared__ float red[256];
    const float* lg = g_logits + (size_t)b * VOCABN;
    float mx = -1e30f;
    for (int i = tid; i < VOCABN; i += 256) mx = fmaxf(mx, lg[i]);
    red[tid] = mx; __syncthreads();
    for (int st = 128; st > 0; st >>= 1) {
        if (tid < st) red[tid] = fmaxf(red[tid], red[tid + st]);
        __syncthreads();
    }
    mx = red[0]; __syncthreads();
    float s = 0.f;
    for (int i = tid; i < VOCABN; i += 256) s += expf(lg[i] - mx);
    red[tid] = s; __syncthreads();
    for (int st = 128; st > 0; st >>= 1) {
        if (tid < st) red[tid] += red[tid + st];
        __syncthreads();
    }
    float inv = 1.f / red[0];
    for (int i = tid; i < VOCABN; i += 256) out[(size_t)b * VOCABN + i] = expf(lg[i] - mx) * inv;
}

// ---------------- host launcher ----------------
static float* sym(const void* s) {
    void* p = nullptr;
    cudaGetSymbolAddress(&p, s);
    return (float*)p;
}

extern "C" void kernel_launch(void* const* d_in, const int* in_sizes, int n_in,
                              void* d_out, int out_size) {
    const float* ques  = (const float*)d_in[0];
    const float* img   = (const float*)d_in[1];
    const float* W_ih  = (const float*)d_in[2];
    const float* W_hh  = (const float*)d_in[3];
    const float* b_ih  = (const float*)d_in[4];
    const float* b_hh  = (const float*)d_in[5];
    const float* Wq1   = (const float*)d_in[6];
    const float* bq1   = (const float*)d_in[7];
    const float* Wq2   = (const float*)d_in[8];
    const float* bq2   = (const float*)d_in[9];
    const float* Wi1   = (const float*)d_in[10];
    const float* bi1   = (const float*)d_in[11];
    const float* Wi2   = (const float*)d_in[12];
    const float* bi2   = (const float*)d_in[13];
    const float* Wp    = (const float*)d_in[14];
    const float* bp    = (const float*)d_in[15];
    const int* h1x = (const int*)d_in[16];
    const int* s1x = (const int*)d_in[17];
    const int* h1q = (const int*)d_in[18];
    const int* s1q = (const int*)d_in[19];
    const int* h2i = (const int*)d_in[20];
    const int* s2i = (const int*)d_in[21];
    const int* h2q = (const int*)d_in[22];
    const int* s2q = (const int*)d_in[23];
    float* out = (float*)d_out;

    float* p_xW    = sym(g_xW);
    float* p_hs    = sym(g_hs);
    float* p_qa1   = sym(g_qa1);
    float* p_qa2   = sym(g_qa2);
    float* p_qatt  = sym(g_qatt);
    float* p_ia1   = sym(g_ia1);
    float* p_ia2   = sym(g_ia2);
    float* p_iatt  = sym(g_iatt);
    float* p_iqn   = sym(g_iqn);
    float* p_z2n   = sym(g_z2n);
    float* p_logits= sym(g_logits);

    cudaFuncSetAttribute(conv1_k, cudaFuncAttributeMaxDynamicSharedMemorySize, CONV_SMEM);

    // init + preprocessing independent of LSTM
    init_state_k<<<(BB*HH + 255)/256, 256>>>();
    zero_csx_k<<<(BB*D1N + 255)/256, 256>>>();
    bin_h_k<<<1, 256>>>(h1q);

    // xW = ques_embed @ W_ih^T + b_ih + b_hh
    {
        dim3 g(G4/64, (TT*BB + 63)/64, 1);
        sgemm<<<g, 256>>>(ques, W_ih, b_ih, b_hh, p_xW,
                          TT*BB, G4, EE, BB, EE, TT*EE, 1, 0);
    }
    scatter1<<<(BB*SS*FEATN + 255)/256, 256>>>(img, h1x, s1x);
    pool1<<<(BB*D1N + 255)/256, 256>>>();

    // LSTM recurrence (fused step kernel)
    for (int t = 0; t < TT; t++)
        lstm_step<<<128, 256>>>(W_hh, t);

    // question attention
    {
        dim3 g(512/64, (TT*BB + 63)/64, 1);
        sgemm<<<g, 256>>>(p_hs, Wq1, bq1, nullptr, p_qa1,
                          TT*BB, 512, HH, 1, HH, 0, 1, 1);
    }
    att2_k<<<TT*BB, 128>>>(p_qa1, Wq2, bq2, p_qa2, TT, 0);
    softmax_small<<<BB*2, 64>>>(p_qa2, p_qatt, TT);
    {
        dim3 g(BB, 2);
        qfeat_k<<<g, 256>>>(s1q, s2q);
    }
    permq_k<<<BB, 256>>>();

    // MCB1 conv (smem-window, 2 blocks/SM) + normalize
    {
        dim3 g(MON/MTILE, BB);
        conv1_k<<<g, CTHREADS, CONV_SMEM>>>();
    }
    norm1_k<<<BB, 256>>>();
    scale1_k<<<(BB*IQN + 255)/256, 256>>>();

    // image attention
    {
        dim3 g(512/64, (BB*SS + 63)/64, 1);
        sgemm<<<g, 256>>>(p_iqn, Wi1, bi1, nullptr, p_ia1,
                          BB*SS, 512, MON, SS, IQN, 1, SS, 1);
    }
    att2_k<<<BB*SS, 128>>>(p_ia1, Wi2, bi2, p_ia2, SS, 1);
    softmax_small<<<BB*2, 64>>>(p_ia2, p_iatt, SS);
    {
        dim3 g(BB, FEATN/256);
        ifeat_k<<<g, 256>>>(img);
    }

    // MCB2 fused
    mcb2_k<<<BB, 256>>>(h2i, s2i, h2q);

    // classifier + softmax
    {
        dim3 g((VOCABN + 63)/64, 1, 1);
        sgemm<<<g, 256>>>(p_z2n, Wp, bp, nullptr, p_logits,
                          BB, VOCABN, MON, 1, MON, 0, 1, 0);
    }
    softmax_out<<<BB, 256>>>(out);
}

// round 7
// speedup vs baseline: 1.2326x; 1.2326x over previous
#include <cuda_runtime.h>
#include <math.h>

#define BB 64
#define TT 26
#define EE 300
#define HH 1024
#define G4 4096
#define FEATN 2048
#define SS 49
#define D1N 245000
#define D2N 5000
#define MON 1000
#define VOCABN 3000
#define QDIM 2048
#define IDIM 4096
#define IQN (MON*SS)

// conv1 tiling: 20 bins, 40-m tiles -> 2 blocks/SM
#define BIN1 12250
#define NBINS 20
#define MTILE 40
#define CTHREADS 640
#define WSZ 21872
#define CONV_SMEM (WSZ*4 + QDIM*4 + QDIM*4)

// ---------------- scratch (device globals) ----------------
__device__ float g_xW[TT*BB*G4];
__device__ float g_gates[4*BB*G4];
__device__ float g_h[BB*HH];
__device__ float g_c[BB*HH];
__device__ float g_hs[TT*BB*HH];
__device__ float g_qa1[TT*BB*512];
__device__ float g_qa2[BB*2*TT];
__device__ float g_qatt[BB*2*TT];
__device__ float g_qfeat[BB*QDIM];
__device__ float g_qv1[BB*QDIM];
__device__ float g_qv2[BB*QDIM];
__device__ float g_qp1[BB*QDIM];
__device__ float g_csx[BB*D1N];
__device__ float g_P1[BB*D1N];
__device__ float g_iq[BB*IQN];
__device__ float g_nrm1[BB];
__device__ float g_iqn[BB*IQN];
__device__ float g_ia1[BB*SS*512];
__device__ float g_ia2[BB*2*SS];
__device__ float g_iatt[BB*2*SS];
__device__ float g_ifeat[BB*IDIM];
__device__ float g_z2n[BB*MON];
__device__ float g_logits[BB*VOCABN];
__device__ int   g_binoff[NBINS+1];
__device__ int   g_perm[QDIM];
__device__ int   g_hperm[QDIM];

__device__ __forceinline__ float sigmoidf_(float x) { return 1.f / (1.f + expf(-x)); }

// ---------------- init ----------------
__global__ void init_state_k() {
    int i = blockIdx.x * 256 + threadIdx.x;
    if (i < BB * HH) { g_h[i] = 0.f; g_c[i] = 0.f; }
}
__global__ void zero_csx_k() {
    int i = blockIdx.x * 256 + threadIdx.x;
    if (i < BB * D1N) g_csx[i] = 0.f;
}

// ---------------- bin h1q ----------------
__global__ void bin_h_k(const int* __restrict__ h1q) {
    __shared__ int cnt[NBINS];
    __shared__ int ofs[NBINS];
    int tid = threadIdx.x;
    if (tid < NBINS) cnt[tid] = 0;
    __syncthreads();
    for (int j = tid; j < QDIM; j += 256) atomicAdd(&cnt[h1q[j] / BIN1], 1);
    __syncthreads();
    if (tid == 0) {
        int s = 0;
        for (int k = 0; k < NBINS; k++) { g_binoff[k] = s; ofs[k] = s; s += cnt[k]; }
        g_binoff[NBINS] = s;
    }
    __syncthreads();
    for (int j = tid; j < QDIM; j += 256) {
        int h = h1q[j];
        int p = atomicAdd(&ofs[h / BIN1], 1);
        g_perm[p] = j;
        g_hperm[p] = h;
    }
}

__global__ void permq_k() {
    int b = blockIdx.x;
    for (int i = threadIdx.x; i < QDIM; i += 256)
        g_qp1[b * QDIM + i] = g_qv1[b * QDIM + g_perm[i]];
}

// ---------------- generic tiled SGEMM ----------------
__global__ void sgemm(const float* __restrict__ A, const float* __restrict__ W,
                      const float* __restrict__ bias1, const float* __restrict__ bias2,
                      float* __restrict__ C,
                      int M, int N, int K, int RD, int S1, int S2, int kstride, int relu)
{
    __shared__ float As[16][64];
    __shared__ float Bs[16][64];
    const int bn = blockIdx.x * 64;
    const int bm = blockIdx.y * 64;
    const int tid = threadIdx.x;
    const int tm = (tid / 16) * 4;
    const int tn = (tid % 16) * 4;

    int kPer = (K + gridDim.z - 1) / gridDim.z;
    int kBeg = blockIdx.z * kPer;
    int kEnd = min(K, kBeg + kPer);

    float acc[4][4];
#pragma unroll
    for (int i = 0; i < 4; i++)
#pragma unroll
        for (int j = 0; j < 4; j++) acc[i][j] = 0.f;

    const int lm = tid >> 2;
    const int lk = (tid & 3) << 2;

    for (int k0 = kBeg; k0 < kEnd; k0 += 16) {
        {
            int row = bm + lm;
            float va[4] = {0.f, 0.f, 0.f, 0.f};
            if (row < M) {
                size_t base = (size_t)(row / RD) * S1 + (size_t)(row % RD) * S2;
                int kg = k0 + lk;
#pragma unroll
                for (int i = 0; i < 4; i++)
                    if (kg + i < kEnd) va[i] = A[base + (size_t)(kg + i) * kstride];
            }
#pragma unroll
            for (int i = 0; i < 4; i++) As[lk + i][lm] = va[i];
        }
        {
            int col = bn + lm;
            float vb[4] = {0.f, 0.f, 0.f, 0.f};
            if (col < N) {
                int kg = k0 + lk;
#pragma unroll
                for (int i = 0; i < 4; i++)
                    if (kg + i < kEnd) vb[i] = W[(size_t)col * K + kg + i];
            }
#pragma unroll
            for (int i = 0; i < 4; i++) Bs[lk + i][lm] = vb[i];
        }
        __syncthreads();
#pragma unroll
        for (int k = 0; k < 16; k++) {
            float4 av = *(const float4*)&As[k][tm];
            float4 bv = *(const float4*)&Bs[k][tn];
            float a4[4] = {av.x, av.y, av.z, av.w};
            float b4[4] = {bv.x, bv.y, bv.z, bv.w};
#pragma unroll
            for (int i = 0; i < 4; i++)
#pragma unroll
                for (int j = 0; j < 4; j++) acc[i][j] += a4[i] * b4[j];
        }
        __syncthreads();
    }

    float* Cz = C + (size_t)blockIdx.z * M * N;
#pragma unroll
    for (int i = 0; i < 4; i++) {
        int row = bm + tm + i;
        if (row >= M) continue;
#pragma unroll
        for (int j = 0; j < 4; j++) {
            int col = bn + tn + j;
            if (col >= N) continue;
            float v = acc[i][j];
            if (blockIdx.z == 0) {
                if (bias1) v += bias1[col];
                if (bias2) v += bias2[col];
            }
            if (relu) v = fmaxf(v, 0.f);
            Cz[(size_t)row * N + col] = v;
        }
    }
}

// ---------------- LSTM pointwise (sums 4 split-K partials) ----------------
__global__ void lstm_point(int t) {
    int id = blockIdx.x * 256 + threadIdx.x;
    if (id >= BB * HH) return;
    int b = id >> 10, hi = id & 1023;
    const float* xw = g_xW + (size_t)(t * BB + b) * G4;
    const float* z0 = g_gates + (size_t)b * G4;
    const float* z1 = g_gates + (size_t)(BB + b) * G4;
    const float* z2 = g_gates + (size_t)(2 * BB + b) * G4;
    const float* z3 = g_gates + (size_t)(3 * BB + b) * G4;
    float gi = xw[hi]        + z0[hi]        + z1[hi]        + z2[hi]        + z3[hi];
    float gf = xw[1024 + hi] + z0[1024 + hi] + z1[1024 + hi] + z2[1024 + hi] + z3[1024 + hi];
    float gg = xw[2048 + hi] + z0[2048 + hi] + z1[2048 + hi] + z2[2048 + hi] + z3[2048 + hi];
    float go = xw[3072 + hi] + z0[3072 + hi] + z1[3072 + hi] + z2[3072 + hi] + z3[3072 + hi];
    float cn = sigmoidf_(gf) * g_c[id] + sigmoidf_(gi) * tanhf(gg);
    float hn = sigmoidf_(go) * tanhf(cn);
    g_c[id] = cn; g_h[id] = hn;
    g_hs[(size_t)t * BB * HH + id] = hn;
}

// ---------------- 2-channel 1x1 conv (512 -> 2) ----------------
__global__ void att2_k(const float* __restrict__ X, const float* __restrict__ W2,
                       const float* __restrict__ b2, float* __restrict__ out,
                       int L, int bdiv) {
    int r = blockIdx.x;
    const float* a = X + (size_t)r * 512;
    float s0 = 0.f, s1 = 0.f;
    for (int o = threadIdx.x; o < 512; o += 128) {
        float v = a[o];
        s0 += W2[o] * v; s1 += W2[512 + o] * v;
    }
    __shared__ float r0[128], r1[128];
    r0[threadIdx.x] = s0; r1[threadIdx.x] = s1; __syncthreads();
    for (int st = 64; st > 0; st >>= 1) {
        if (threadIdx.x < st) { r0[threadIdx.x] += r0[threadIdx.x + st]; r1[threadIdx.x] += r1[threadIdx.x + st]; }
        __syncthreads();
    }
    if (threadIdx.x == 0) {
        int b, l;
        if (bdiv == 0) { b = r & 63; l = r >> 6; }
        else { b = r / 49; l = r % 49; }
        out[(b * 2 + 0) * L + l] = r0[0] + b2[0];
        out[(b * 2 + 1) * L + l] = r1[0] + b2[1];
    }
}

// ---------------- small row softmax (n <= 64), 64 threads ----------------
__global__ void softmax_small(const float* __restrict__ in, float* __restrict__ out, int n) {
    __shared__ float sm[64];
    int r = blockIdx.x, tid = threadIdx.x;
    float v = (tid < n) ? in[(size_t)r * n + tid] : -1e30f;
    sm[tid] = v; __syncthreads();
    for (int st = 32; st > 0; st >>= 1) {
        if (tid < st) sm[tid] = fmaxf(sm[tid], sm[tid + st]);
        __syncthreads();
    }
    float mx = sm[0]; __syncthreads();
    float e = (tid < n) ? expf(v - mx) : 0.f;
    sm[tid] = e; __syncthreads();
    for (int st = 32; st > 0; st >>= 1) {
        if (tid < st) sm[tid] += sm[tid + st];
        __syncthreads();
    }
    if (tid < n) out[(size_t)r * n + tid] = e / sm[0];
}

// ---------------- question feature + signed copies ----------------
__global__ void qfeat_k(const int* __restrict__ s1q, const int* __restrict__ s2q) {
    int b = blockIdx.x, g = blockIdx.y;
    __shared__ float att[TT];
    if (threadIdx.x < TT) att[threadIdx.x] = g_qatt[(b * 2 + g) * TT + threadIdx.x];
    __syncthreads();
    for (int h = threadIdx.x; h < HH; h += blockDim.x) {
        float acc = 0.f;
        for (int t = 0; t < TT; t++)
            acc += att[t] * g_hs[((size_t)t * BB + b) * HH + h];
        int j = g * HH + h;
        g_qfeat[b * QDIM + j] = acc;
        g_qv1[b * QDIM + j] = acc * (float)(2 * s1q[j] - 1);
        g_qv2[b * QDIM + j] = acc * (float)(2 * s2q[j] - 1);
    }
}

// ---------------- MCB1: scatter, pool ----------------
__global__ void scatter1(const float* __restrict__ img, const int* __restrict__ h1x,
                         const int* __restrict__ s1x) {
    int id = blockIdx.x * 256 + threadIdx.x;
    if (id >= BB * SS * FEATN) return;
    int f = id % FEATN;
    int r = id / FEATN;
    int s = r % SS, b = r / SS;
    int n = f * SS + s;
    float v = img[id] * (float)(2 * s1x[n] - 1);
    atomicAdd(&g_csx[(size_t)b * D1N + h1x[n]], v);
}

__global__ void pool1() {
    int id = blockIdx.x * 256 + threadIdx.x;
    if (id >= BB * D1N) return;
    int t = id % D1N; int b = id / D1N;
    const float* cs = g_csx + (size_t)b * D1N;
    float a = 0.f;
#pragma unroll
    for (int f = 0; f < 5; f++) {
        int tt = t + 49 * f;
        if (tt >= D1N) tt -= D1N;
        a += cs[tt];
    }
    g_P1[id] = a;
}

// ---------------- MCB1 conv: smem window over bins ----------------
__global__ void conv1_k() {
    extern __shared__ float smw[];
    float* win = smw;                    // [WSZ]
    float* sq  = smw + WSZ;              // [QDIM]
    int*   sh  = (int*)(sq + QDIM);      // [QDIM]
    int b = blockIdx.y;
    int m0 = blockIdx.x * MTILE;
    int tid = threadIdx.x;

    for (int i = tid; i < QDIM; i += CTHREADS) {
        sq[i] = g_qp1[b * QDIM + i];
        sh[i] = g_hperm[i];
    }

    int mg = tid >> 6;
    int sl = tid & 63;
    bool lane_ok = sl < 49;
    int offb = 245 * mg + sl;
    float acc[4] = {0.f, 0.f, 0.f, 0.f};
    const float* Pb = g_P1 + (size_t)b * D1N;
    int T0 = 245 * m0;

    for (int k = 0; k < NBINS; k++) {
        __syncthreads();
        int W0 = T0 - (k + 1) * BIN1 + 1;
        W0 %= D1N; if (W0 < 0) W0 += D1N;
        for (int i = tid; i < WSZ; i += CTHREADS) {
            int g = W0 + i; if (g >= D1N) g -= D1N;
            win[i] = Pb[g];
        }
        __syncthreads();
        int j0 = g_binoff[k], j1 = g_binoff[k + 1];
        if (lane_ok) {
            int base0 = (k + 1) * BIN1 - 1 + offb;
            for (int j = j0; j < j1; j++) {
                float q = sq[j];
                int a = base0 - sh[j];
#pragma unroll
                for (int it = 0; it < 4; it++)
                    acc[it] += q * win[a + 2450 * it];
            }
        }
    }

    if (lane_ok) {
#pragma unroll
        for (int it = 0; it < 4; it++) {
            int m = mg + 10 * it;
            g_iq[(size_t)b * IQN + (m0 + m) * 49 + sl] = acc[it];
        }
    }
}

__global__ void norm1_k() {
    int b = blockIdx.x, tid = threadIdx.x;
    __shared__ float red[256];
    float s = 0.f;
    const float* x = g_iq + (size_t)b * IQN;
    for (int i = tid; i < IQN; i += 256) s += fabsf(x[i]);
    red[tid] = s; __syncthreads();
    for (int st = 128; st > 0; st >>= 1) {
        if (tid < st) red[tid] += red[tid + st];
        __syncthreads();
    }
    if (tid == 0) g_nrm1[b] = 1.f / fmaxf(sqrtf(red[0]), 1e-12f);
}

__global__ void scale1_k() {
    int id = blockIdx.x * 256 + threadIdx.x;
    if (id >= BB * IQN) return;
    int b = id / IQN;
    float x = g_iq[id];
    g_iqn[id] = copysignf(sqrtf(fabsf(x)), x) * g_nrm1[b];
}

// ---------------- image feature ----------------
__global__ void ifeat_k(const float* __restrict__ img) {
    int b = blockIdx.x;
    __shared__ float a0[SS], a1[SS];
    if (threadIdx.x < SS) {
        a0[threadIdx.x] = g_iatt[(b * 2 + 0) * SS + threadIdx.x];
        a1[threadIdx.x] = g_iatt[(b * 2 + 1) * SS + threadIdx.x];
    }
    __syncthreads();
    int f = blockIdx.y * 256 + threadIdx.x;
    float acc0 = 0.f, acc1 = 0.f;
    for (int s = 0; s < SS; s++) {
        float v = img[((size_t)b * SS + s) * FEATN + f];
        acc0 += a0[s] * v; acc1 += a1[s] * v;
    }
    g_ifeat[b * IDIM + f] = acc0;
    g_ifeat[b * IDIM + FEATN + f] = acc1;
}

// ---------------- MCB2 fully fused ----------------
__global__ void mcb2_k(const int* __restrict__ h2i, const int* __restrict__ s2i,
                       const int* __restrict__ h2q) {
    __shared__ float cs[D2N];
    __shared__ float sq[QDIM];
    __shared__ int   shh[QDIM];
    __shared__ float red[256];
    int b = blockIdx.x, tid = threadIdx.x;
    for (int i = tid; i < D2N; i += 256) cs[i] = 0.f;
    for (int j = tid; j < QDIM; j += 256) { sq[j] = g_qv2[b * QDIM + j]; shh[j] = h2q[j]; }
    __syncthreads();
    for (int n = tid; n < IDIM; n += 256) {
        float v = g_ifeat[b * IDIM + n] * (float)(2 * s2i[n] - 1);
        atomicAdd(&cs[h2i[n]], v);
    }
    __syncthreads();
    float p[20];
#pragma unroll
    for (int k = 0; k < 20; k++) {
        int t = tid + k * 256;
        float a = 0.f;
        if (t < D2N) {
#pragma unroll
            for (int f = 0; f < 5; f++) { int u = t + f; if (u >= D2N) u -= D2N; a += cs[u]; }
        }
        p[k] = a;
    }
    __syncthreads();
#pragma unroll
    for (int k = 0; k < 20; k++) { int t = tid + k * 256; if (t < D2N) cs[t] = p[k]; }
    __syncthreads();
    float z[4] = {0.f, 0.f, 0.f, 0.f};
    int mb[4];
#pragma unroll
    for (int k = 0; k < 4; k++) { int m = tid + k * 256; mb[k] = (m < MON) ? 5 * m : 0; }
    for (int j = 0; j < QDIM; j++) {
        int h = shh[j]; float q = sq[j];
#pragma unroll
        for (int k = 0; k < 4; k++) { int d = mb[k] - h; if (d < 0) d += D2N; z[k] += q * cs[d]; }
    }
    float sa = 0.f;
#pragma unroll
    for (int k = 0; k < 4; k++) { if (tid + k * 256 < MON) sa += fabsf(z[k]); }
    red[tid] = sa; __syncthreads();
    for (int st = 128; st > 0; st >>= 1) {
        if (tid < st) red[tid] += red[tid + st];
        __syncthreads();
    }
    float inv = 1.f / fmaxf(sqrtf(red[0]), 1e-12f);
#pragma unroll
    for (int k = 0; k < 4; k++) {
        int m = tid + k * 256;
        if (m < MON) g_z2n[b * MON + m] = copysignf(sqrtf(fabsf(z[k])), z[k]) * inv;
    }
}

// ---------------- final softmax (3000) ----------------
__global__ void softmax_out(float* __restrict__ out) {
    int b = blockIdx.x, tid = threadIdx.x;
    __shared__ float red[256];
    const float* lg = g_logits + (size_t)b * VOCABN;
    float mx = -1e30f;
    for (int i = tid; i < VOCABN; i += 256) mx = fmaxf(mx, lg[i]);
    red[tid] = mx; __syncthreads();
    for (int st = 128; st > 0; st >>= 1) {
        if (tid < st) red[tid] = fmaxf(red[tid], red[tid + st]);
        __syncthreads();
    }
    mx = red[0]; __syncthreads();
    float s = 0.f;
    for (int i = tid; i < VOCABN; i += 256) s += expf(lg[i] - mx);
    red[tid] = s; __syncthreads();
    for (int st = 128; st > 0; st >>= 1) {
        if (tid < st) red[tid] += red[tid + st];
        __syncthreads();
    }
    float inv = 1.f / red[0];
    for (int i = tid; i < VOCABN; i += 256) out[(size_t)b * VOCABN + i] = expf(lg[i] - mx) * inv;
}

// ---------------- host launcher ----------------
static float* sym(const void* s) {
    void* p = nullptr;
    cudaGetSymbolAddress(&p, s);
    return (float*)p;
}

extern "C" void kernel_launch(void* const* d_in, const int* in_sizes, int n_in,
                              void* d_out, int out_size) {
    const float* ques  = (const float*)d_in[0];
    const float* img   = (const float*)d_in[1];
    const float* W_ih  = (const float*)d_in[2];
    const float* W_hh  = (const float*)d_in[3];
    const float* b_ih  = (const float*)d_in[4];
    const float* b_hh  = (const float*)d_in[5];
    const float* Wq1   = (const float*)d_in[6];
    const float* bq1   = (const float*)d_in[7];
    const float* Wq2   = (const float*)d_in[8];
    const float* bq2   = (const float*)d_in[9];
    const float* Wi1   = (const float*)d_in[10];
    const float* bi1   = (const float*)d_in[11];
    const float* Wi2   = (const float*)d_in[12];
    const float* bi2   = (const float*)d_in[13];
    const float* Wp    = (const float*)d_in[14];
    const float* bp    = (const float*)d_in[15];
    const int* h1x = (const int*)d_in[16];
    const int* s1x = (const int*)d_in[17];
    const int* h1q = (const int*)d_in[18];
    const int* s1q = (const int*)d_in[19];
    const int* h2i = (const int*)d_in[20];
    const int* s2i = (const int*)d_in[21];
    const int* h2q = (const int*)d_in[22];
    const int* s2q = (const int*)d_in[23];
    float* out = (float*)d_out;

    float* p_xW    = sym(g_xW);
    float* p_gates = sym(g_gates);
    float* p_h     = sym(g_h);
    float* p_hs    = sym(g_hs);
    float* p_qa1   = sym(g_qa1);
    float* p_qa2   = sym(g_qa2);
    float* p_qatt  = sym(g_qatt);
    float* p_ia1   = sym(g_ia1);
    float* p_ia2   = sym(g_ia2);
    float* p_iatt  = sym(g_iatt);
    float* p_iqn   = sym(g_iqn);
    float* p_z2n   = sym(g_z2n);
    float* p_logits= sym(g_logits);

    cudaFuncSetAttribute(conv1_k, cudaFuncAttributeMaxDynamicSharedMemorySize, CONV_SMEM);

    // init + preprocessing independent of LSTM
    init_state_k<<<(BB*HH + 255)/256, 256>>>();
    zero_csx_k<<<(BB*D1N + 255)/256, 256>>>();
    bin_h_k<<<1, 256>>>(h1q);

    // xW = ques_embed @ W_ih^T + b_ih + b_hh
    {
        dim3 g(G4/64, (TT*BB + 63)/64, 1);
        sgemm<<<g, 256>>>(ques, W_ih, b_ih, b_hh, p_xW,
                          TT*BB, G4, EE, BB, EE, TT*EE, 1, 0);
    }
    scatter1<<<(BB*SS*FEATN + 255)/256, 256>>>(img, h1x, s1x);
    pool1<<<(BB*D1N + 255)/256, 256>>>();

    // LSTM recurrence (split-K 4) — reverted to R3-proven path
    for (int t = 0; t < TT; t++) {
        dim3 g(G4/64, 1, 4);
        sgemm<<<g, 256>>>(p_h, W_hh, nullptr, nullptr, p_gates,
                          BB, G4, HH, 1, HH, 0, 1, 0);
        lstm_point<<<(BB*HH + 255)/256, 256>>>(t);
    }

    // question attention
    {
        dim3 g(512/64, (TT*BB + 63)/64, 1);
        sgemm<<<g, 256>>>(p_hs, Wq1, bq1, nullptr, p_qa1,
                          TT*BB, 512, HH, 1, HH, 0, 1, 1);
    }
    att2_k<<<TT*BB, 128>>>(p_qa1, Wq2, bq2, p_qa2, TT, 0);
    softmax_small<<<BB*2, 64>>>(p_qa2, p_qatt, TT);
    {
        dim3 g(BB, 2);
        qfeat_k<<<g, 256>>>(s1q, s2q);
    }
    permq_k<<<BB, 256>>>();

    // MCB1 conv (smem-window, 2 blocks/SM) + normalize
    {
        dim3 g(MON/MTILE, BB);
        conv1_k<<<g, CTHREADS, CONV_SMEM>>>();
    }
    norm1_k<<<BB, 256>>>();
    scale1_k<<<(BB*IQN + 255)/256, 256>>>();

    // image attention
    {
        dim3 g(512/64, (BB*SS + 63)/64, 1);
        sgemm<<<g, 256>>>(p_iqn, Wi1, bi1, nullptr, p_ia1,
                          BB*SS, 512, MON, SS, IQN, 1, SS, 1);
    }
    att2_k<<<BB*SS, 128>>>(p_ia1, Wi2, bi2, p_ia2, SS, 1);
    softmax_small<<<BB*2, 64>>>(p_ia2, p_iatt, SS);
    {
        dim3 g(BB, FEATN/256);
        ifeat_k<<<g, 256>>>(img);
    }

    // MCB2 fused
    mcb2_k<<<BB, 256>>>(h2i, s2i, h2q);

    // classifier + softmax
    {
        dim3 g((VOCABN + 63)/64, 1, 1);
        sgemm<<<g, 256>>>(p_z2n, Wp, bp, nullptr, p_logits,
                          BB, VOCABN, MON, 1, MON, 0, 1, 0);
    }
    softmax_out<<<BB, 256>>>(out);
}

// round 8
// speedup vs baseline: 1.2637x; 1.0252x over previous
#include <cuda_runtime.h>
#include <math.h>

#define BB 64
#define TT 26
#define EE 300
#define HH 1024
#define G4 4096
#define FEATN 2048
#define SS 49
#define D1N 245000
#define D2N 5000
#define MON 1000
#define VOCABN 3000
#define QDIM 2048
#define IDIM 4096
#define IQN (MON*SS)

// conv1 tiling: 10 bins, 65-m tiles, 49-lane mapping (637/640 active)
#define BIN1 24500
#define NBINS 10
#define MTILE 65
#define CTHREADS 640
// max smem index: (BIN1-1) + (245*12+48) + 3185*4 = 40227
#define WSZ 40232
#define CONV_SMEM (WSZ*4 + QDIM*4 + QDIM*4)

// ---------------- scratch (device globals) ----------------
__device__ float g_xW[TT*BB*G4];
__device__ float g_gates[4*BB*G4];
__device__ float g_h[BB*HH];
__device__ float g_c[BB*HH];
__device__ float g_hs[TT*BB*HH];
__device__ float g_qa1[TT*BB*512];
__device__ float g_qa2[BB*2*TT];
__device__ float g_qatt[BB*2*TT];
__device__ float g_qfeat[BB*QDIM];
__device__ float g_qv1[BB*QDIM];
__device__ float g_qv2[BB*QDIM];
__device__ float g_qp1[BB*QDIM];
__device__ float g_csx[BB*D1N];
__device__ float g_P1[BB*D1N];
__device__ float g_iq[BB*IQN];
__device__ float g_nrm1[BB];
__device__ float g_iqn[BB*IQN];
__device__ float g_ia1[BB*SS*512];
__device__ float g_ia2[BB*2*SS];
__device__ float g_iatt[BB*2*SS];
__device__ float g_ifeat[BB*IDIM];
__device__ float g_z2n[BB*MON];
__device__ float g_logits[BB*VOCABN];
__device__ int   g_binoff[NBINS+1];
__device__ int   g_perm[QDIM];
__device__ int   g_hperm[QDIM];

__device__ __forceinline__ float sigmoidf_(float x) { return 1.f / (1.f + expf(-x)); }

// ---------------- init ----------------
__global__ void init_state_k() {
    int i = blockIdx.x * 256 + threadIdx.x;
    if (i < BB * HH) { g_h[i] = 0.f; g_c[i] = 0.f; }
}
__global__ void zero_csx_k() {
    int i = blockIdx.x * 256 + threadIdx.x;
    if (i < BB * D1N) g_csx[i] = 0.f;
}

// ---------------- bin h1q ----------------
__global__ void bin_h_k(const int* __restrict__ h1q) {
    __shared__ int cnt[NBINS];
    __shared__ int ofs[NBINS];
    int tid = threadIdx.x;
    if (tid < NBINS) cnt[tid] = 0;
    __syncthreads();
    for (int j = tid; j < QDIM; j += 256) atomicAdd(&cnt[h1q[j] / BIN1], 1);
    __syncthreads();
    if (tid == 0) {
        int s = 0;
        for (int k = 0; k < NBINS; k++) { g_binoff[k] = s; ofs[k] = s; s += cnt[k]; }
        g_binoff[NBINS] = s;
    }
    __syncthreads();
    for (int j = tid; j < QDIM; j += 256) {
        int h = h1q[j];
        int p = atomicAdd(&ofs[h / BIN1], 1);
        g_perm[p] = j;
        g_hperm[p] = h;
    }
}

__global__ void permq_k() {
    int b = blockIdx.x;
    for (int i = threadIdx.x; i < QDIM; i += 256)
        g_qp1[b * QDIM + i] = g_qv1[b * QDIM + g_perm[i]];
}

// ---------------- generic tiled SGEMM ----------------
__global__ void sgemm(const float* __restrict__ A, const float* __restrict__ W,
                      const float* __restrict__ bias1, const float* __restrict__ bias2,
                      float* __restrict__ C,
                      int M, int N, int K, int RD, int S1, int S2, int kstride, int relu)
{
    __shared__ float As[16][64];
    __shared__ float Bs[16][64];
    const int bn = blockIdx.x * 64;
    const int bm = blockIdx.y * 64;
    const int tid = threadIdx.x;
    const int tm = (tid / 16) * 4;
    const int tn = (tid % 16) * 4;

    int kPer = (K + gridDim.z - 1) / gridDim.z;
    int kBeg = blockIdx.z * kPer;
    int kEnd = min(K, kBeg + kPer);

    float acc[4][4];
#pragma unroll
    for (int i = 0; i < 4; i++)
#pragma unroll
        for (int j = 0; j < 4; j++) acc[i][j] = 0.f;

    const int lm = tid >> 2;
    const int lk = (tid & 3) << 2;

    for (int k0 = kBeg; k0 < kEnd; k0 += 16) {
        {
            int row = bm + lm;
            float va[4] = {0.f, 0.f, 0.f, 0.f};
            if (row < M) {
                size_t base = (size_t)(row / RD) * S1 + (size_t)(row % RD) * S2;
                int kg = k0 + lk;
#pragma unroll
                for (int i = 0; i < 4; i++)
                    if (kg + i < kEnd) va[i] = A[base + (size_t)(kg + i) * kstride];
            }
#pragma unroll
            for (int i = 0; i < 4; i++) As[lk + i][lm] = va[i];
        }
        {
            int col = bn + lm;
            float vb[4] = {0.f, 0.f, 0.f, 0.f};
            if (col < N) {
                int kg = k0 + lk;
#pragma unroll
                for (int i = 0; i < 4; i++)
                    if (kg + i < kEnd) vb[i] = W[(size_t)col * K + kg + i];
            }
#pragma unroll
            for (int i = 0; i < 4; i++) Bs[lk + i][lm] = vb[i];
        }
        __syncthreads();
#pragma unroll
        for (int k = 0; k < 16; k++) {
            float4 av = *(const float4*)&As[k][tm];
            float4 bv = *(const float4*)&Bs[k][tn];
            float a4[4] = {av.x, av.y, av.z, av.w};
            float b4[4] = {bv.x, bv.y, bv.z, bv.w};
#pragma unroll
            for (int i = 0; i < 4; i++)
#pragma unroll
                for (int j = 0; j < 4; j++) acc[i][j] += a4[i] * b4[j];
        }
        __syncthreads();
    }

    float* Cz = C + (size_t)blockIdx.z * M * N;
#pragma unroll
    for (int i = 0; i < 4; i++) {
        int row = bm + tm + i;
        if (row >= M) continue;
#pragma unroll
        for (int j = 0; j < 4; j++) {
            int col = bn + tn + j;
            if (col >= N) continue;
            float v = acc[i][j];
            if (blockIdx.z == 0) {
                if (bias1) v += bias1[col];
                if (bias2) v += bias2[col];
            }
            if (relu) v = fmaxf(v, 0.f);
            Cz[(size_t)row * N + col] = v;
        }
    }
}

// ---------------- LSTM pointwise (sums 4 split-K partials) ----------------
__global__ void lstm_point(int t) {
    int id = blockIdx.x * 256 + threadIdx.x;
    if (id >= BB * HH) return;
    int b = id >> 10, hi = id & 1023;
    const float* xw = g_xW + (size_t)(t * BB + b) * G4;
    const float* z0 = g_gates + (size_t)b * G4;
    const float* z1 = g_gates + (size_t)(BB + b) * G4;
    const float* z2 = g_gates + (size_t)(2 * BB + b) * G4;
    const float* z3 = g_gates + (size_t)(3 * BB + b) * G4;
    float gi = xw[hi]        + z0[hi]        + z1[hi]        + z2[hi]        + z3[hi];
    float gf = xw[1024 + hi] + z0[1024 + hi] + z1[1024 + hi] + z2[1024 + hi] + z3[1024 + hi];
    float gg = xw[2048 + hi] + z0[2048 + hi] + z1[2048 + hi] + z2[2048 + hi] + z3[2048 + hi];
    float go = xw[3072 + hi] + z0[3072 + hi] + z1[3072 + hi] + z2[3072 + hi] + z3[3072 + hi];
    float cn = sigmoidf_(gf) * g_c[id] + sigmoidf_(gi) * tanhf(gg);
    float hn = sigmoidf_(go) * tanhf(cn);
    g_c[id] = cn; g_h[id] = hn;
    g_hs[(size_t)t * BB * HH + id] = hn;
}

// ---------------- 2-channel 1x1 conv (512 -> 2) ----------------
__global__ void att2_k(const float* __restrict__ X, const float* __restrict__ W2,
                       const float* __restrict__ b2, float* __restrict__ out,
                       int L, int bdiv) {
    int r = blockIdx.x;
    const float* a = X + (size_t)r * 512;
    float s0 = 0.f, s1 = 0.f;
    for (int o = threadIdx.x; o < 512; o += 128) {
        float v = a[o];
        s0 += W2[o] * v; s1 += W2[512 + o] * v;
    }
    __shared__ float r0[128], r1[128];
    r0[threadIdx.x] = s0; r1[threadIdx.x] = s1; __syncthreads();
    for (int st = 64; st > 0; st >>= 1) {
        if (threadIdx.x < st) { r0[threadIdx.x] += r0[threadIdx.x + st]; r1[threadIdx.x] += r1[threadIdx.x + st]; }
        __syncthreads();
    }
    if (threadIdx.x == 0) {
        int b, l;
        if (bdiv == 0) { b = r & 63; l = r >> 6; }
        else { b = r / 49; l = r % 49; }
        out[(b * 2 + 0) * L + l] = r0[0] + b2[0];
        out[(b * 2 + 1) * L + l] = r1[0] + b2[1];
    }
}

// ---------------- small row softmax (n <= 64), 64 threads ----------------
__global__ void softmax_small(const float* __restrict__ in, float* __restrict__ out, int n) {
    __shared__ float sm[64];
    int r = blockIdx.x, tid = threadIdx.x;
    float v = (tid < n) ? in[(size_t)r * n + tid] : -1e30f;
    sm[tid] = v; __syncthreads();
    for (int st = 32; st > 0; st >>= 1) {
        if (tid < st) sm[tid] = fmaxf(sm[tid], sm[tid + st]);
        __syncthreads();
    }
    float mx = sm[0]; __syncthreads();
    float e = (tid < n) ? expf(v - mx) : 0.f;
    sm[tid] = e; __syncthreads();
    for (int st = 32; st > 0; st >>= 1) {
        if (tid < st) sm[tid] += sm[tid + st];
        __syncthreads();
    }
    if (tid < n) out[(size_t)r * n + tid] = e / sm[0];
}

// ---------------- question feature + signed copies ----------------
__global__ void qfeat_k(const int* __restrict__ s1q, const int* __restrict__ s2q) {
    int b = blockIdx.x, g = blockIdx.y;
    __shared__ float att[TT];
    if (threadIdx.x < TT) att[threadIdx.x] = g_qatt[(b * 2 + g) * TT + threadIdx.x];
    __syncthreads();
    for (int h = threadIdx.x; h < HH; h += blockDim.x) {
        float acc = 0.f;
        for (int t = 0; t < TT; t++)
            acc += att[t] * g_hs[((size_t)t * BB + b) * HH + h];
        int j = g * HH + h;
        g_qfeat[b * QDIM + j] = acc;
        g_qv1[b * QDIM + j] = acc * (float)(2 * s1q[j] - 1);
        g_qv2[b * QDIM + j] = acc * (float)(2 * s2q[j] - 1);
    }
}

// ---------------- MCB1: scatter, pool ----------------
__global__ void scatter1(const float* __restrict__ img, const int* __restrict__ h1x,
                         const int* __restrict__ s1x) {
    int id = blockIdx.x * 256 + threadIdx.x;
    if (id >= BB * SS * FEATN) return;
    int f = id % FEATN;
    int r = id / FEATN;
    int s = r % SS, b = r / SS;
    int n = f * SS + s;
    float v = img[id] * (float)(2 * s1x[n] - 1);
    atomicAdd(&g_csx[(size_t)b * D1N + h1x[n]], v);
}

__global__ void pool1() {
    int id = blockIdx.x * 256 + threadIdx.x;
    if (id >= BB * D1N) return;
    int t = id % D1N; int b = id / D1N;
    const float* cs = g_csx + (size_t)b * D1N;
    float a = 0.f;
#pragma unroll
    for (int f = 0; f < 5; f++) {
        int tt = t + 49 * f;
        if (tt >= D1N) tt -= D1N;
        a += cs[tt];
    }
    g_P1[id] = a;
}

// ---------------- MCB1 conv: smem window, 49-lane mapping ----------------
// 640 threads: mg = tid/49 in [0,13), sl = tid%49. Thread handles m = mg + 13*it, it<5.
__global__ void conv1_k() {
    extern __shared__ float smw[];
    float* win = smw;                    // [WSZ]
    float* sq  = smw + WSZ;              // [QDIM]
    int*   sh  = (int*)(sq + QDIM);      // [QDIM]
    int b = blockIdx.y;
    int m0 = blockIdx.x * MTILE;
    int tid = threadIdx.x;

    for (int i = tid; i < QDIM; i += CTHREADS) {
        sq[i] = g_qp1[b * QDIM + i];
        sh[i] = g_hperm[i];
    }

    int mg = tid / 49;
    int sl = tid - mg * 49;
    bool lane_ok = mg < 13;
    int offb = 245 * mg + sl;
    float acc[5] = {0.f, 0.f, 0.f, 0.f, 0.f};
    const float* Pb = g_P1 + (size_t)b * D1N;
    int T0 = 245 * m0;

    for (int k = 0; k < NBINS; k++) {
        __syncthreads();
        int W0 = T0 - (k + 1) * BIN1 + 1;
        W0 %= D1N; if (W0 < 0) W0 += D1N;
        for (int i = tid; i < WSZ; i += CTHREADS) {
            int g = W0 + i; if (g >= D1N) g -= D1N;
            win[i] = Pb[g];
        }
        __syncthreads();
        int j0 = g_binoff[k], j1 = g_binoff[k + 1];
        if (lane_ok) {
            int base0 = (k + 1) * BIN1 - 1 + offb;
            for (int j = j0; j < j1; j++) {
                float q = sq[j];
                int a = base0 - sh[j];
#pragma unroll
                for (int it = 0; it < 5; it++)
                    acc[it] += q * win[a + 3185 * it];
            }
        }
    }

    if (lane_ok) {
#pragma unroll
        for (int it = 0; it < 5; it++) {
            int m = mg + 13 * it;
            if (m0 + m < MON)
                g_iq[(size_t)b * IQN + (m0 + m) * 49 + sl] = acc[it];
        }
    }
}

__global__ void norm1_k() {
    int b = blockIdx.x, tid = threadIdx.x;
    __shared__ float red[256];
    float s = 0.f;
    const float* x = g_iq + (size_t)b * IQN;
    for (int i = tid; i < IQN; i += 256) s += fabsf(x[i]);
    red[tid] = s; __syncthreads();
    for (int st = 128; st > 0; st >>= 1) {
        if (tid < st) red[tid] += red[tid + st];
        __syncthreads();
    }
    if (tid == 0) g_nrm1[b] = 1.f / fmaxf(sqrtf(red[0]), 1e-12f);
}

__global__ void scale1_k() {
    int id = blockIdx.x * 256 + threadIdx.x;
    if (id >= BB * IQN) return;
    int b = id / IQN;
    float x = g_iq[id];
    g_iqn[id] = copysignf(sqrtf(fabsf(x)), x) * g_nrm1[b];
}

// ---------------- image feature ----------------
__global__ void ifeat_k(const float* __restrict__ img) {
    int b = blockIdx.x;
    __shared__ float a0[SS], a1[SS];
    if (threadIdx.x < SS) {
        a0[threadIdx.x] = g_iatt[(b * 2 + 0) * SS + threadIdx.x];
        a1[threadIdx.x] = g_iatt[(b * 2 + 1) * SS + threadIdx.x];
    }
    __syncthreads();
    int f = blockIdx.y * 256 + threadIdx.x;
    float acc0 = 0.f, acc1 = 0.f;
    for (int s = 0; s < SS; s++) {
        float v = img[((size_t)b * SS + s) * FEATN + f];
        acc0 += a0[s] * v; acc1 += a1[s] * v;
    }
    g_ifeat[b * IDIM + f] = acc0;
    g_ifeat[b * IDIM + FEATN + f] = acc1;
}

// ---------------- MCB2 fully fused ----------------
__global__ void mcb2_k(const int* __restrict__ h2i, const int* __restrict__ s2i,
                       const int* __restrict__ h2q) {
    __shared__ float cs[D2N];
    __shared__ float sq[QDIM];
    __shared__ int   shh[QDIM];
    __shared__ float red[256];
    int b = blockIdx.x, tid = threadIdx.x;
    for (int i = tid; i < D2N; i += 256) cs[i] = 0.f;
    for (int j = tid; j < QDIM; j += 256) { sq[j] = g_qv2[b * QDIM + j]; shh[j] = h2q[j]; }
    __syncthreads();
    for (int n = tid; n < IDIM; n += 256) {
        float v = g_ifeat[b * IDIM + n] * (float)(2 * s2i[n] - 1);
        atomicAdd(&cs[h2i[n]], v);
    }
    __syncthreads();
    float p[20];
#pragma unroll
    for (int k = 0; k < 20; k++) {
        int t = tid + k * 256;
        float a = 0.f;
        if (t < D2N) {
#pragma unroll
            for (int f = 0; f < 5; f++) { int u = t + f; if (u >= D2N) u -= D2N; a += cs[u]; }
        }
        p[k] = a;
    }
    __syncthreads();
#pragma unroll
    for (int k = 0; k < 20; k++) { int t = tid + k * 256; if (t < D2N) cs[t] = p[k]; }
    __syncthreads();
    float z[4] = {0.f, 0.f, 0.f, 0.f};
    int mb[4];
#pragma unroll
    for (int k = 0; k < 4; k++) { int m = tid + k * 256; mb[k] = (m < MON) ? 5 * m : 0; }
    for (int j = 0; j < QDIM; j++) {
        int h = shh[j]; float q = sq[j];
#pragma unroll
        for (int k = 0; k < 4; k++) { int d = mb[k] - h; if (d < 0) d += D2N; z[k] += q * cs[d]; }
    }
    float sa = 0.f;
#pragma unroll
    for (int k = 0; k < 4; k++) { if (tid + k * 256 < MON) sa += fabsf(z[k]); }
    red[tid] = sa; __syncthreads();
    for (int st = 128; st > 0; st >>= 1) {
        if (tid < st) red[tid] += red[tid + st];
        __syncthreads();
    }
    float inv = 1.f / fmaxf(sqrtf(red[0]), 1e-12f);
#pragma unroll
    for (int k = 0; k < 4; k++) {
        int m = tid + k * 256;
        if (m < MON) g_z2n[b * MON + m] = copysignf(sqrtf(fabsf(z[k])), z[k]) * inv;
    }
}

// ---------------- final softmax (3000) ----------------
__global__ void softmax_out(float* __restrict__ out) {
    int b = blockIdx.x, tid = threadIdx.x;
    __shared__ float red[256];
    const float* lg = g_logits + (size_t)b * VOCABN;
    float mx = -1e30f;
    for (int i = tid; i < VOCABN; i += 256) mx = fmaxf(mx, lg[i]);
    red[tid] = mx; __syncthreads();
    for (int st = 128; st > 0; st >>= 1) {
        if (tid < st) red[tid] = fmaxf(red[tid], red[tid + st]);
        __syncthreads();
    }
    mx = red[0]; __syncthreads();
    float s = 0.f;
    for (int i = tid; i < VOCABN; i += 256) s += expf(lg[i] - mx);
    red[tid] = s; __syncthreads();
    for (int st = 128; st > 0; st >>= 1) {
        if (tid < st) red[tid] += red[tid + st];
        __syncthreads();
    }
    float inv = 1.f / red[0];
    for (int i = tid; i < VOCABN; i += 256) out[(size_t)b * VOCABN + i] = expf(lg[i] - mx) * inv;
}

// ---------------- host launcher ----------------
static float* sym(const void* s) {
    void* p = nullptr;
    cudaGetSymbolAddress(&p, s);
    return (float*)p;
}

extern "C" void kernel_launch(void* const* d_in, const int* in_sizes, int n_in,
                              void* d_out, int out_size) {
    const float* ques  = (const float*)d_in[0];
    const float* img   = (const float*)d_in[1];
    const float* W_ih  = (const float*)d_in[2];
    const float* W_hh  = (const float*)d_in[3];
    const float* b_ih  = (const float*)d_in[4];
    const float* b_hh  = (const float*)d_in[5];
    const float* Wq1   = (const float*)d_in[6];
    const float* bq1   = (const float*)d_in[7];
    const float* Wq2   = (const float*)d_in[8];
    const float* bq2   = (const float*)d_in[9];
    const float* Wi1   = (const float*)d_in[10];
    const float* bi1   = (const float*)d_in[11];
    const float* Wi2   = (const float*)d_in[12];
    const float* bi2   = (const float*)d_in[13];
    const float* Wp    = (const float*)d_in[14];
    const float* bp    = (const float*)d_in[15];
    const int* h1x = (const int*)d_in[16];
    const int* s1x = (const int*)d_in[17];
    const int* h1q = (const int*)d_in[18];
    const int* s1q = (const int*)d_in[19];
    const int* h2i = (const int*)d_in[20];
    const int* s2i = (const int*)d_in[21];
    const int* h2q = (const int*)d_in[22];
    const int* s2q = (const int*)d_in[23];
    float* out = (float*)d_out;

    float* p_xW    = sym(g_xW);
    float* p_gates = sym(g_gates);
    float* p_h     = sym(g_h);
    float* p_hs    = sym(g_hs);
    float* p_qa1   = sym(g_qa1);
    float* p_qa2   = sym(g_qa2);
    float* p_qatt  = sym(g_qatt);
    float* p_ia1   = sym(g_ia1);
    float* p_ia2   = sym(g_ia2);
    float* p_iatt  = sym(g_iatt);
    float* p_iqn   = sym(g_iqn);
    float* p_z2n   = sym(g_z2n);
    float* p_logits= sym(g_logits);

    cudaFuncSetAttribute(conv1_k, cudaFuncAttributeMaxDynamicSharedMemorySize, CONV_SMEM);

    // init + preprocessing independent of LSTM
    init_state_k<<<(BB*HH + 255)/256, 256>>>();
    zero_csx_k<<<(BB*D1N + 255)/256, 256>>>();
    bin_h_k<<<1, 256>>>(h1q);

    // xW = ques_embed @ W_ih^T + b_ih + b_hh
    {
        dim3 g(G4/64, (TT*BB + 63)/64, 1);
        sgemm<<<g, 256>>>(ques, W_ih, b_ih, b_hh, p_xW,
                          TT*BB, G4, EE, BB, EE, TT*EE, 1, 0);
    }
    scatter1<<<(BB*SS*FEATN + 255)/256, 256>>>(img, h1x, s1x);
    pool1<<<(BB*D1N + 255)/256, 256>>>();

    // LSTM recurrence (split-K 4)
    for (int t = 0; t < TT; t++) {
        dim3 g(G4/64, 1, 4);
        sgemm<<<g, 256>>>(p_h, W_hh, nullptr, nullptr, p_gates,
                          BB, G4, HH, 1, HH, 0, 1, 0);
        lstm_point<<<(BB*HH + 255)/256, 256>>>(t);
    }

    // question attention
    {
        dim3 g(512/64, (TT*BB + 63)/64, 1);
        sgemm<<<g, 256>>>(p_hs, Wq1, bq1, nullptr, p_qa1,
                          TT*BB, 512, HH, 1, HH, 0, 1, 1);
    }
    att2_k<<<TT*BB, 128>>>(p_qa1, Wq2, bq2, p_qa2, TT, 0);
    softmax_small<<<BB*2, 64>>>(p_qa2, p_qatt, TT);
    {
        dim3 g(BB, 2);
        qfeat_k<<<g, 256>>>(s1q, s2q);
    }
    permq_k<<<BB, 256>>>();

    // MCB1 conv (49-lane smem-window) + normalize
    {
        dim3 g((MON + MTILE - 1)/MTILE, BB);
        conv1_k<<<g, CTHREADS, CONV_SMEM>>>();
    }
    norm1_k<<<BB, 256>>>();
    scale1_k<<<(BB*IQN + 255)/256, 256>>>();

    // image attention
    {
        dim3 g(512/64, (BB*SS + 63)/64, 1);
        sgemm<<<g, 256>>>(p_iqn, Wi1, bi1, nullptr, p_ia1,
                          BB*SS, 512, MON, SS, IQN, 1, SS, 1);
    }
    att2_k<<<BB*SS, 128>>>(p_ia1, Wi2, bi2, p_ia2, SS, 1);
    softmax_small<<<BB*2, 64>>>(p_ia2, p_iatt, SS);
    {
        dim3 g(BB, FEATN/256);
        ifeat_k<<<g, 256>>>(img);
    }

    // MCB2 fused
    mcb2_k<<<BB, 256>>>(h2i, s2i, h2q);

    // classifier + softmax
    {
        dim3 g((VOCABN + 63)/64, 1, 1);
        sgemm<<<g, 256>>>(p_z2n, Wp, bp, nullptr, p_logits,
                          BB, VOCABN, MON, 1, MON, 0, 1, 0);
    }
    softmax_out<<<BB, 256>>>(out);
}

// round 9
// speedup vs baseline: 1.3428x; 1.0626x over previous
#include <cuda_runtime.h>
#include <math.h>

#define BB 64
#define TT 26
#define EE 300
#define HH 1024
#define G4 4096
#define FEATN 2048
#define SS 49
#define D1N 245000
#define D2N 5000
#define MON 1000
#define VOCABN 3000
#define QDIM 2048
#define IDIM 4096
#define IQN (MON*SS)

// conv1 tiling (R3-proven): 10 bins, 65-m tiles, 64-lane mapping
#define BIN1 24500
#define NBINS 10
#define MTILE 65
#define CTHREADS 640
#define WSZ 41504
#define CONV_SMEM (WSZ*4 + QDIM*4 + QDIM*4)

// ---------------- scratch (device globals) ----------------
__device__ float g_xW[TT*BB*G4];
__device__ float g_gates[4*BB*G4];
__device__ float g_c[BB*HH];
__device__ float g_hs[TT*BB*HH];
__device__ int   g_cnt[64];
__device__ float g_qa1[TT*BB*512];
__device__ float g_qa2[BB*2*TT];
__device__ float g_qatt[BB*2*TT];
__device__ float g_qfeat[BB*QDIM];
__device__ float g_qv1[BB*QDIM];
__device__ float g_qv2[BB*QDIM];
__device__ float g_qp1[BB*QDIM];
__device__ float g_csx[BB*D1N];
__device__ float g_P1[BB*D1N];
__device__ float g_iq[BB*IQN];
__device__ float g_nrm1[BB];
__device__ float g_iqn[BB*IQN];
__device__ float g_ia1[BB*SS*512];
__device__ float g_ia2[BB*2*SS];
__device__ float g_iatt[BB*2*SS];
__device__ float g_ifeat[BB*IDIM];
__device__ float g_z2n[BB*MON];
__device__ float g_logits[BB*VOCABN];
__device__ int   g_binoff[NBINS+1];
__device__ int   g_perm[QDIM];
__device__ int   g_hperm[QDIM];

__device__ __forceinline__ float sigmoidf_(float x) { return 1.f / (1.f + expf(-x)); }

// ---------------- init ----------------
__global__ void init_state_k() {
    int i = blockIdx.x * 256 + threadIdx.x;
    if (i < BB * HH) g_c[i] = 0.f;
    if (i < 64) g_cnt[i] = 0;
}
__global__ void zero_csx_k() {
    int i = blockIdx.x * 256 + threadIdx.x;
    if (i < BB * D1N) g_csx[i] = 0.f;
}

// ---------------- bin h1q ----------------
__global__ void bin_h_k(const int* __restrict__ h1q) {
    __shared__ int cnt[NBINS];
    __shared__ int ofs[NBINS];
    int tid = threadIdx.x;
    if (tid < NBINS) cnt[tid] = 0;
    __syncthreads();
    for (int j = tid; j < QDIM; j += 256) atomicAdd(&cnt[h1q[j] / BIN1], 1);
    __syncthreads();
    if (tid == 0) {
        int s = 0;
        for (int k = 0; k < NBINS; k++) { g_binoff[k] = s; ofs[k] = s; s += cnt[k]; }
        g_binoff[NBINS] = s;
    }
    __syncthreads();
    for (int j = tid; j < QDIM; j += 256) {
        int h = h1q[j];
        int p = atomicAdd(&ofs[h / BIN1], 1);
        g_perm[p] = j;
        g_hperm[p] = h;
    }
}

__global__ void permq_k() {
    int b = blockIdx.x;
    for (int i = threadIdx.x; i < QDIM; i += 256)
        g_qp1[b * QDIM + i] = g_qv1[b * QDIM + g_perm[i]];
}

// ---------------- generic tiled SGEMM ----------------
__global__ void sgemm(const float* __restrict__ A, const float* __restrict__ W,
                      const float* __restrict__ bias1, const float* __restrict__ bias2,
                      float* __restrict__ C,
                      int M, int N, int K, int RD, int S1, int S2, int kstride, int relu)
{
    __shared__ float As[16][64];
    __shared__ float Bs[16][64];
    const int bn = blockIdx.x * 64;
    const int bm = blockIdx.y * 64;
    const int tid = threadIdx.x;
    const int tm = (tid / 16) * 4;
    const int tn = (tid % 16) * 4;

    int kPer = (K + gridDim.z - 1) / gridDim.z;
    int kBeg = blockIdx.z * kPer;
    int kEnd = min(K, kBeg + kPer);

    float acc[4][4];
#pragma unroll
    for (int i = 0; i < 4; i++)
#pragma unroll
        for (int j = 0; j < 4; j++) acc[i][j] = 0.f;

    const int lm = tid >> 2;
    const int lk = (tid & 3) << 2;

    for (int k0 = kBeg; k0 < kEnd; k0 += 16) {
        {
            int row = bm + lm;
            float va[4] = {0.f, 0.f, 0.f, 0.f};
            if (row < M) {
                size_t base = (size_t)(row / RD) * S1 + (size_t)(row % RD) * S2;
                int kg = k0 + lk;
#pragma unroll
                for (int i = 0; i < 4; i++)
                    if (kg + i < kEnd) va[i] = A[base + (size_t)(kg + i) * kstride];
            }
#pragma unroll
            for (int i = 0; i < 4; i++) As[lk + i][lm] = va[i];
        }
        {
            int col = bn + lm;
            float vb[4] = {0.f, 0.f, 0.f, 0.f};
            if (col < N) {
                int kg = k0 + lk;
#pragma unroll
                for (int i = 0; i < 4; i++)
                    if (kg + i < kEnd) vb[i] = W[(size_t)col * K + kg + i];
            }
#pragma unroll
            for (int i = 0; i < 4; i++) Bs[lk + i][lm] = vb[i];
        }
        __syncthreads();
#pragma unroll
        for (int k = 0; k < 16; k++) {
            float4 av = *(const float4*)&As[k][tm];
            float4 bv = *(const float4*)&Bs[k][tn];
            float a4[4] = {av.x, av.y, av.z, av.w};
            float b4[4] = {bv.x, bv.y, bv.z, bv.w};
#pragma unroll
            for (int i = 0; i < 4; i++)
#pragma unroll
                for (int j = 0; j < 4; j++) acc[i][j] += a4[i] * b4[j];
        }
        __syncthreads();
    }

    float* Cz = C + (size_t)blockIdx.z * M * N;
#pragma unroll
    for (int i = 0; i < 4; i++) {
        int row = bm + tm + i;
        if (row >= M) continue;
#pragma unroll
        for (int j = 0; j < 4; j++) {
            int col = bn + tn + j;
            if (col >= N) continue;
            float v = acc[i][j];
            if (blockIdx.z == 0) {
                if (bias1) v += bias1[col];
                if (bias2) v += bias2[col];
            }
            if (relu) v = fmaxf(v, 0.f);
            Cz[(size_t)row * N + col] = v;
        }
    }
}

// ---------------- fused LSTM step (GEMM + last-block gate epilogue) ----------------
// grid (64 ctiles, 4 k-slices). Columns interleaved: c = h*4 + g -> W row g*HH + h.
// ctile ct covers h in [16ct, 16ct+16), all 4 gates.
__global__ __launch_bounds__(256) void lstm_fused(const float* __restrict__ W_hh, int t) {
    __shared__ float As[16][64];
    __shared__ float Bs[16][64];
    __shared__ int s_last;
    const int ct = blockIdx.x;
    const int z = blockIdx.y;
    const int bn = ct * 64;
    const int tid = threadIdx.x;
    const int tm = (tid / 16) * 4;
    const int tn = (tid % 16) * 4;

    float acc[4][4];
#pragma unroll
    for (int i = 0; i < 4; i++)
#pragma unroll
        for (int j = 0; j < 4; j++) acc[i][j] = 0.f;

    if (t > 0) {
        const float* hprev = g_hs + (size_t)(t - 1) * BB * HH;
        const int lm = tid >> 2;
        const int lk = (tid & 3) << 2;
        int kBeg = z * 256;
        for (int k0 = kBeg; k0 < kBeg + 256; k0 += 16) {
            {
                int kg = k0 + lk;
                float4 va = *(const float4*)&hprev[lm * HH + kg];
                As[lk + 0][lm] = va.x; As[lk + 1][lm] = va.y;
                As[lk + 2][lm] = va.z; As[lk + 3][lm] = va.w;
            }
            {
                int col = bn + lm;
                int r = (col & 3) * HH + (col >> 2);
                int kg = k0 + lk;
                float4 vb = *(const float4*)&W_hh[(size_t)r * HH + kg];
                Bs[lk + 0][lm] = vb.x; Bs[lk + 1][lm] = vb.y;
                Bs[lk + 2][lm] = vb.z; Bs[lk + 3][lm] = vb.w;
            }
            __syncthreads();
#pragma unroll
            for (int k = 0; k < 16; k++) {
                float4 av = *(const float4*)&As[k][tm];
                float4 bv = *(const float4*)&Bs[k][tn];
                float a4[4] = {av.x, av.y, av.z, av.w};
                float b4[4] = {bv.x, bv.y, bv.z, bv.w};
#pragma unroll
                for (int i = 0; i < 4; i++)
#pragma unroll
                    for (int j = 0; j < 4; j++) acc[i][j] += a4[i] * b4[j];
            }
            __syncthreads();
        }
    }

    // write partial (interleaved column index)
    float* Pz = g_gates + (size_t)z * BB * G4;
#pragma unroll
    for (int i = 0; i < 4; i++)
#pragma unroll
        for (int j = 0; j < 4; j++)
            Pz[(size_t)(tm + i) * G4 + bn + tn + j] = acc[i][j];

    __threadfence();
    __syncthreads();
    if (tid == 0) {
        int d = atomicAdd(&g_cnt[ct], 1);
        s_last = (d == 3) ? 1 : 0;
    }
    __syncthreads();
    if (!s_last) return;
    __threadfence();
    if (tid == 0) g_cnt[ct] = 0;   // reset for next step (stream-ordered)

    // epilogue: 64 batches x 16 h-units
#pragma unroll
    for (int i = 0; i < 4; i++) {
        int idx = tid + 256 * i;       // 0..1023
        int b = idx >> 4;
        int hl = idx & 15;
        int h = ct * 16 + hl;
        const float* xw = g_xW + (size_t)(t * BB + b) * G4;
        float gv[4];
#pragma unroll
        for (int g = 0; g < 4; g++) {
            int c = bn + hl * 4 + g;
            float s = __ldcg(&g_gates[(size_t)b * G4 + c])
                    + __ldcg(&g_gates[(size_t)(BB + b) * G4 + c])
                    + __ldcg(&g_gates[(size_t)(2 * BB + b) * G4 + c])
                    + __ldcg(&g_gates[(size_t)(3 * BB + b) * G4 + c]);
            gv[g] = s + xw[g * HH + h];
        }
        int id = b * HH + h;
        float cn = sigmoidf_(gv[1]) * g_c[id] + sigmoidf_(gv[0]) * tanhf(gv[2]);
        float hn = sigmoidf_(gv[3]) * tanhf(cn);
        g_c[id] = cn;
        g_hs[(size_t)t * BB * HH + id] = hn;
    }
}

// ---------------- 2-channel 1x1 conv (512 -> 2) ----------------
__global__ void att2_k(const float* __restrict__ X, const float* __restrict__ W2,
                       const float* __restrict__ b2, float* __restrict__ out,
                       int L, int bdiv) {
    int r = blockIdx.x;
    const float* a = X + (size_t)r * 512;
    float s0 = 0.f, s1 = 0.f;
    for (int o = threadIdx.x; o < 512; o += 128) {
        float v = a[o];
        s0 += W2[o] * v; s1 += W2[512 + o] * v;
    }
    __shared__ float r0[128], r1[128];
    r0[threadIdx.x] = s0; r1[threadIdx.x] = s1; __syncthreads();
    for (int st = 64; st > 0; st >>= 1) {
        if (threadIdx.x < st) { r0[threadIdx.x] += r0[threadIdx.x + st]; r1[threadIdx.x] += r1[threadIdx.x + st]; }
        __syncthreads();
    }
    if (threadIdx.x == 0) {
        int b, l;
        if (bdiv == 0) { b = r & 63; l = r >> 6; }
        else { b = r / 49; l = r % 49; }
        out[(b * 2 + 0) * L + l] = r0[0] + b2[0];
        out[(b * 2 + 1) * L + l] = r1[0] + b2[1];
    }
}

// ---------------- small row softmax (n <= 64), 64 threads ----------------
__global__ void softmax_small(const float* __restrict__ in, float* __restrict__ out, int n) {
    __shared__ float sm[64];
    int r = blockIdx.x, tid = threadIdx.x;
    float v = (tid < n) ? in[(size_t)r * n + tid] : -1e30f;
    sm[tid] = v; __syncthreads();
    for (int st = 32; st > 0; st >>= 1) {
        if (tid < st) sm[tid] = fmaxf(sm[tid], sm[tid + st]);
        __syncthreads();
    }
    float mx = sm[0]; __syncthreads();
    float e = (tid < n) ? expf(v - mx) : 0.f;
    sm[tid] = e; __syncthreads();
    for (int st = 32; st > 0; st >>= 1) {
        if (tid < st) sm[tid] += sm[tid + st];
        __syncthreads();
    }
    if (tid < n) out[(size_t)r * n + tid] = e / sm[0];
}

// ---------------- question feature + signed copies ----------------
__global__ void qfeat_k(const int* __restrict__ s1q, const int* __restrict__ s2q) {
    int b = blockIdx.x, g = blockIdx.y;
    __shared__ float att[TT];
    if (threadIdx.x < TT) att[threadIdx.x] = g_qatt[(b * 2 + g) * TT + threadIdx.x];
    __syncthreads();
    for (int h = threadIdx.x; h < HH; h += blockDim.x) {
        float acc = 0.f;
        for (int t = 0; t < TT; t++)
            acc += att[t] * g_hs[((size_t)t * BB + b) * HH + h];
        int j = g * HH + h;
        g_qfeat[b * QDIM + j] = acc;
        g_qv1[b * QDIM + j] = acc * (float)(2 * s1q[j] - 1);
        g_qv2[b * QDIM + j] = acc * (float)(2 * s2q[j] - 1);
    }
}

// ---------------- MCB1: scatter, pool ----------------
__global__ void scatter1(const float* __restrict__ img, const int* __restrict__ h1x,
                         const int* __restrict__ s1x) {
    int id = blockIdx.x * 256 + threadIdx.x;
    if (id >= BB * SS * FEATN) return;
    int f = id % FEATN;
    int r = id / FEATN;
    int s = r % SS, b = r / SS;
    int n = f * SS + s;
    float v = img[id] * (float)(2 * s1x[n] - 1);
    atomicAdd(&g_csx[(size_t)b * D1N + h1x[n]], v);
}

__global__ void pool1() {
    int id = blockIdx.x * 256 + threadIdx.x;
    if (id >= BB * D1N) return;
    int t = id % D1N; int b = id / D1N;
    const float* cs = g_csx + (size_t)b * D1N;
    float a = 0.f;
#pragma unroll
    for (int f = 0; f < 5; f++) {
        int tt = t + 49 * f;
        if (tt >= D1N) tt -= D1N;
        a += cs[tt];
    }
    g_P1[id] = a;
}

// ---------------- MCB1 conv: smem window over bins (R3-proven config) ----------------
__global__ void conv1_k() {
    extern __shared__ float smw[];
    float* win = smw;                    // [WSZ]
    float* sq  = smw + WSZ;              // [QDIM]
    int*   sh  = (int*)(sq + QDIM);      // [QDIM]
    int b = blockIdx.y;
    int m0 = blockIdx.x * MTILE;
    int tid = threadIdx.x;

    for (int i = tid; i < QDIM; i += CTHREADS) {
        sq[i] = g_qp1[b * QDIM + i];
        sh[i] = g_hperm[i];
    }

    int mg = tid >> 6;
    int sl = tid & 63;
    bool lane_ok = sl < 49;
    int offb = 245 * mg + sl;
    float acc[7] = {0.f, 0.f, 0.f, 0.f, 0.f, 0.f, 0.f};
    const float* Pb = g_P1 + (size_t)b * D1N;
    int T0 = 245 * m0;

    for (int k = 0; k < NBINS; k++) {
        __syncthreads();
        int W0 = T0 - (k + 1) * BIN1 + 1;
        W0 %= D1N; if (W0 < 0) W0 += D1N;
        for (int i = tid; i < WSZ; i += CTHREADS) {
            int g = W0 + i; if (g >= D1N) g -= D1N;
            win[i] = Pb[g];
        }
        __syncthreads();
        int j0 = g_binoff[k], j1 = g_binoff[k + 1];
        if (lane_ok) {
            int base0 = (k + 1) * BIN1 - 1 + offb;
            for (int j = j0; j < j1; j++) {
                float q = sq[j];
                int a = base0 - sh[j];
#pragma unroll
                for (int it = 0; it < 7; it++)
                    acc[it] += q * win[a + 2450 * it];
            }
        }
    }

    if (lane_ok) {
#pragma unroll
        for (int it = 0; it < 7; it++) {
            int m = mg + 10 * it;
            if (m < MTILE && m0 + m < MON)
                g_iq[(size_t)b * IQN + (m0 + m) * 49 + sl] = acc[it];
        }
    }
}

__global__ void norm1_k() {
    int b = blockIdx.x, tid = threadIdx.x;
    __shared__ float red[256];
    float s = 0.f;
    const float* x = g_iq + (size_t)b * IQN;
    for (int i = tid; i < IQN; i += 256) s += fabsf(x[i]);
    red[tid] = s; __syncthreads();
    for (int st = 128; st > 0; st >>= 1) {
        if (tid < st) red[tid] += red[tid + st];
        __syncthreads();
    }
    if (tid == 0) g_nrm1[b] = 1.f / fmaxf(sqrtf(red[0]), 1e-12f);
}

__global__ void scale1_k() {
    int id = blockIdx.x * 256 + threadIdx.x;
    if (id >= BB * IQN) return;
    int b = id / IQN;
    float x = g_iq[id];
    g_iqn[id] = copysignf(sqrtf(fabsf(x)), x) * g_nrm1[b];
}

// ---------------- image feature ----------------
__global__ void ifeat_k(const float* __restrict__ img) {
    int b = blockIdx.x;
    __shared__ float a0[SS], a1[SS];
    if (threadIdx.x < SS) {
        a0[threadIdx.x] = g_iatt[(b * 2 + 0) * SS + threadIdx.x];
        a1[threadIdx.x] = g_iatt[(b * 2 + 1) * SS + threadIdx.x];
    }
    __syncthreads();
    int f = blockIdx.y * 256 + threadIdx.x;
    float acc0 = 0.f, acc1 = 0.f;
    for (int s = 0; s < SS; s++) {
        float v = img[((size_t)b * SS + s) * FEATN + f];
        acc0 += a0[s] * v; acc1 += a1[s] * v;
    }
    g_ifeat[b * IDIM + f] = acc0;
    g_ifeat[b * IDIM + FEATN + f] = acc1;
}

// ---------------- MCB2 fully fused ----------------
__global__ void mcb2_k(const int* __restrict__ h2i, const int* __restrict__ s2i,
                       const int* __restrict__ h2q) {
    __shared__ float cs[D2N];
    __shared__ float sq[QDIM];
    __shared__ int   shh[QDIM];
    __shared__ float red[256];
    int b = blockIdx.x, tid = threadIdx.x;
    for (int i = tid; i < D2N; i += 256) cs[i] = 0.f;
    for (int j = tid; j < QDIM; j += 256) { sq[j] = g_qv2[b * QDIM + j]; shh[j] = h2q[j]; }
    __syncthreads();
    for (int n = tid; n < IDIM; n += 256) {
        float v = g_ifeat[b * IDIM + n] * (float)(2 * s2i[n] - 1);
        atomicAdd(&cs[h2i[n]], v);
    }
    __syncthreads();
    float p[20];
#pragma unroll
    for (int k = 0; k < 20; k++) {
        int t = tid + k * 256;
        float a = 0.f;
        if (t < D2N) {
#pragma unroll
            for (int f = 0; f < 5; f++) { int u = t + f; if (u >= D2N) u -= D2N; a += cs[u]; }
        }
        p[k] = a;
    }
    __syncthreads();
#pragma unroll
    for (int k = 0; k < 20; k++) { int t = tid + k * 256; if (t < D2N) cs[t] = p[k]; }
    __syncthreads();
    float z[4] = {0.f, 0.f, 0.f, 0.f};
    int mb[4];
#pragma unroll
    for (int k = 0; k < 4; k++) { int m = tid + k * 256; mb[k] = (m < MON) ? 5 * m : 0; }
    for (int j = 0; j < QDIM; j++) {
        int h = shh[j]; float q = sq[j];
#pragma unroll
        for (int k = 0; k < 4; k++) { int d = mb[k] - h; if (d < 0) d += D2N; z[k] += q * cs[d]; }
    }
    float sa = 0.f;
#pragma unroll
    for (int k = 0; k < 4; k++) { if (tid + k * 256 < MON) sa += fabsf(z[k]); }
    red[tid] = sa; __syncthreads();
    for (int st = 128; st > 0; st >>= 1) {
        if (tid < st) red[tid] += red[tid + st];
        __syncthreads();
    }
    float inv = 1.f / fmaxf(sqrtf(red[0]), 1e-12f);
#pragma unroll
    for (int k = 0; k < 4; k++) {
        int m = tid + k * 256;
        if (m < MON) g_z2n[b * MON + m] = copysignf(sqrtf(fabsf(z[k])), z[k]) * inv;
    }
}

// ---------------- final softmax (3000) ----------------
__global__ void softmax_out(float* __restrict__ out) {
    int b = blockIdx.x, tid = threadIdx.x;
    __shared__ float red[256];
    const float* lg = g_logits + (size_t)b * VOCABN;
    float mx = -1e30f;
    for (int i = tid; i < VOCABN; i += 256) mx = fmaxf(mx, lg[i]);
    red[tid] = mx; __syncthreads();
    for (int st = 128; st > 0; st >>= 1) {
        if (tid < st) red[tid] = fmaxf(red[tid], red[tid + st]);
        __syncthreads();
    }
    mx = red[0]; __syncthreads();
    float s = 0.f;
    for (int i = tid; i < VOCABN; i += 256) s += expf(lg[i] - mx);
    red[tid] = s; __syncthreads();
    for (int st = 128; st > 0; st >>= 1) {
        if (tid < st) red[tid] += red[tid + st];
        __syncthreads();
    }
    float inv = 1.f / red[0];
    for (int i = tid; i < VOCABN; i += 256) out[(size_t)b * VOCABN + i] = expf(lg[i] - mx) * inv;
}

// ---------------- host launcher ----------------
static float* sym(const void* s) {
    void* p = nullptr;
    cudaGetSymbolAddress(&p, s);
    return (float*)p;
}

extern "C" void kernel_launch(void* const* d_in, const int* in_sizes, int n_in,
                              void* d_out, int out_size) {
    const float* ques  = (const float*)d_in[0];
    const float* img   = (const float*)d_in[1];
    const float* W_ih  = (const float*)d_in[2];
    const float* W_hh  = (const float*)d_in[3];
    const float* b_ih  = (const float*)d_in[4];
    const float* b_hh  = (const float*)d_in[5];
    const float* Wq1   = (const float*)d_in[6];
    const float* bq1   = (const float*)d_in[7];
    const float* Wq2   = (const float*)d_in[8];
    const float* bq2   = (const float*)d_in[9];
    const float* Wi1   = (const float*)d_in[10];
    const float* bi1   = (const float*)d_in[11];
    const float* Wi2   = (const float*)d_in[12];
    const float* bi2   = (const float*)d_in[13];
    const float* Wp    = (const float*)d_in[14];
    const float* bp    = (const float*)d_in[15];
    const int* h1x = (const int*)d_in[16];
    const int* s1x = (const int*)d_in[17];
    const int* h1q = (const int*)d_in[18];
    const int* s1q = (const int*)d_in[19];
    const int* h2i = (const int*)d_in[20];
    const int* s2i = (const int*)d_in[21];
    const int* h2q = (const int*)d_in[22];
    const int* s2q = (const int*)d_in[23];
    float* out = (float*)d_out;

    float* p_xW    = sym(g_xW);
    float* p_hs    = sym(g_hs);
    float* p_qa1   = sym(g_qa1);
    float* p_qa2   = sym(g_qa2);
    float* p_qatt  = sym(g_qatt);
    float* p_ia1   = sym(g_ia1);
    float* p_ia2   = sym(g_ia2);
    float* p_iatt  = sym(g_iatt);
    float* p_iqn   = sym(g_iqn);
    float* p_z2n   = sym(g_z2n);
    float* p_logits= sym(g_logits);

    cudaFuncSetAttribute(conv1_k, cudaFuncAttributeMaxDynamicSharedMemorySize, CONV_SMEM);

    // init + preprocessing independent of LSTM
    init_state_k<<<(BB*HH + 255)/256, 256>>>();
    zero_csx_k<<<(BB*D1N + 255)/256, 256>>>();
    bin_h_k<<<1, 256>>>(h1q);

    // xW = ques_embed @ W_ih^T + b_ih + b_hh
    {
        dim3 g(G4/64, (TT*BB + 63)/64, 1);
        sgemm<<<g, 256>>>(ques, W_ih, b_ih, b_hh, p_xW,
                          TT*BB, G4, EE, BB, EE, TT*EE, 1, 0);
    }
    scatter1<<<(BB*SS*FEATN + 255)/256, 256>>>(img, h1x, s1x);
    pool1<<<(BB*D1N + 255)/256, 256>>>();

    // LSTM recurrence (fused GEMM + gate epilogue, split-K 4)
    for (int t = 0; t < TT; t++) {
        dim3 g(64, 4, 1);
        lstm_fused<<<g, 256>>>(W_hh, t);
    }

    // question attention
    {
        dim3 g(512/64, (TT*BB + 63)/64, 1);
        sgemm<<<g, 256>>>(p_hs, Wq1, bq1, nullptr, p_qa1,
                          TT*BB, 512, HH, 1, HH, 0, 1, 1);
    }
    att2_k<<<TT*BB, 128>>>(p_qa1, Wq2, bq2, p_qa2, TT, 0);
    softmax_small<<<BB*2, 64>>>(p_qa2, p_qatt, TT);
    {
        dim3 g(BB, 2);
        qfeat_k<<<g, 256>>>(s1q, s2q);
    }
    permq_k<<<BB, 256>>>();

    // MCB1 conv (R3 config) + normalize
    {
        dim3 g((MON + MTILE - 1)/MTILE, BB);
        conv1_k<<<g, CTHREADS, CONV_SMEM>>>();
    }
    norm1_k<<<BB, 256>>>();
    scale1_k<<<(BB*IQN + 255)/256, 256>>>();

    // image attention
    {
        dim3 g(512/64, (BB*SS + 63)/64, 1);
        sgemm<<<g, 256>>>(p_iqn, Wi1, bi1, nullptr, p_ia1,
                          BB*SS, 512, MON, SS, IQN, 1, SS, 1);
    }
    att2_k<<<BB*SS, 128>>>(p_ia1, Wi2, bi2, p_ia2, SS, 1);
    softmax_small<<<BB*2, 64>>>(p_ia2, p_iatt, SS);
    {
        dim3 g(BB, FEATN/256);
        ifeat_k<<<g, 256>>>(img);
    }

    // MCB2 fused
    mcb2_k<<<BB, 256>>>(h2i, s2i, h2q);

    // classifier + softmax
    {
        dim3 g((VOCABN + 63)/64, 1, 1);
        sgemm<<<g, 256>>>(p_z2n, Wp, bp, nullptr, p_logits,
                          BB, VOCABN, MON, 1, MON, 0, 1, 0);
    }
    softmax_out<<<BB, 256>>>(out);
}

// round 10
// speedup vs baseline: 1.4149x; 1.0537x over previous
#include <cuda_runtime.h>
#include <math.h>

#define BB 64
#define TT 26
#define EE 300
#define HH 1024
#define G4 4096
#define FEATN 2048
#define SS 49
#define D1N 245000
#define D2N 5000
#define MON 1000
#define VOCABN 3000
#define QDIM 2048
#define IDIM 4096
#define IQN (MON*SS)

// conv1 tiling (R3-proven): 10 bins, 65-m tiles, 64-lane mapping + padded bins
#define BIN1 24500
#define NBINS 10
#define MTILE 65
#define CTHREADS 640
#define WSZ 41504
#define JPAD 2080
#define CONV_SMEM (WSZ*4 + JPAD*4 + JPAD*4)

// ---------------- scratch (device globals) ----------------
__device__ float g_xW[TT*BB*G4];
__device__ float g_gates[4*BB*G4];
__device__ float g_c[BB*HH];
__device__ float g_hs[TT*BB*HH];
__device__ int   g_cnt[64];
__device__ float g_qa1[TT*BB*512];
__device__ float g_qa2[BB*2*TT];
__device__ float g_qatt[BB*2*TT];
__device__ float g_qfeat[BB*QDIM];
__device__ float g_qv1[BB*QDIM];
__device__ float g_qv2[BB*QDIM];
__device__ float g_qp1[BB*JPAD];
__device__ float g_csx[BB*D1N];
__device__ float g_P1[BB*D1N];
__device__ float g_iq[BB*IQN];
__device__ float g_nrm1[BB];
__device__ float g_iqn[BB*IQN];
__device__ float g_ia1[BB*SS*512];
__device__ float g_ia2[BB*2*SS];
__device__ float g_iatt[BB*2*SS];
__device__ float g_ifeat[BB*IDIM];
__device__ float g_z2n[BB*MON];
__device__ float g_logits[BB*VOCABN];
__device__ int   g_binoff[NBINS+1];
__device__ int   g_perm[JPAD];
__device__ int   g_hperm[JPAD];

__device__ __forceinline__ float sigmoidf_(float x) { return 1.f / (1.f + expf(-x)); }

// ---------------- init ----------------
__global__ void init_state_k() {
    int i = blockIdx.x * 256 + threadIdx.x;
    if (i < BB * HH) g_c[i] = 0.f;
    if (i < 64) g_cnt[i] = 0;
}
__global__ void zero_csx_k() {
    int i = blockIdx.x * 256 + threadIdx.x;
    if (i < BB * D1N) g_csx[i] = 0.f;
}

// ---------------- bin h1q (bins padded to multiples of 4) ----------------
__global__ void bin_h_k(const int* __restrict__ h1q) {
    __shared__ int cnt[NBINS];
    __shared__ int start[NBINS+1];
    __shared__ int ofs[NBINS];
    int tid = threadIdx.x;
    if (tid < NBINS) cnt[tid] = 0;
    __syncthreads();
    for (int j = tid; j < QDIM; j += 256) atomicAdd(&cnt[h1q[j] / BIN1], 1);
    __syncthreads();
    if (tid == 0) {
        int s = 0;
        for (int k = 0; k < NBINS; k++) {
            start[k] = s; ofs[k] = s;
            g_binoff[k] = s;
            s += (cnt[k] + 3) & ~3;
        }
        start[NBINS] = s;
        g_binoff[NBINS] = s;
    }
    __syncthreads();
    // defaults: perm=-1 everywhere; h = bin floor within each bin's padded span
    for (int i = tid; i < JPAD; i += 256) { g_perm[i] = -1; g_hperm[i] = 0; }
    __syncthreads();
    for (int k = 0; k < NBINS; k++)
        for (int i = start[k] + tid; i < start[k+1]; i += 256)
            g_hperm[i] = k * BIN1;
    __syncthreads();
    for (int j = tid; j < QDIM; j += 256) {
        int h = h1q[j];
        int p = atomicAdd(&ofs[h / BIN1], 1);
        g_perm[p] = j;
        g_hperm[p] = h;
    }
}

__global__ void permq_k() {
    int b = blockIdx.x;
    for (int i = threadIdx.x; i < JPAD; i += 256) {
        int p = g_perm[i];
        g_qp1[b * JPAD + i] = (p >= 0) ? g_qv1[b * QDIM + p] : 0.f;
    }
}

// ---------------- generic tiled SGEMM ----------------
__global__ void sgemm(const float* __restrict__ A, const float* __restrict__ W,
                      const float* __restrict__ bias1, const float* __restrict__ bias2,
                      float* __restrict__ C,
                      int M, int N, int K, int RD, int S1, int S2, int kstride, int relu)
{
    __shared__ float As[16][64];
    __shared__ float Bs[16][64];
    const int bn = blockIdx.x * 64;
    const int bm = blockIdx.y * 64;
    const int tid = threadIdx.x;
    const int tm = (tid / 16) * 4;
    const int tn = (tid % 16) * 4;

    int kPer = (K + gridDim.z - 1) / gridDim.z;
    int kBeg = blockIdx.z * kPer;
    int kEnd = min(K, kBeg + kPer);

    float acc[4][4];
#pragma unroll
    for (int i = 0; i < 4; i++)
#pragma unroll
        for (int j = 0; j < 4; j++) acc[i][j] = 0.f;

    const int lm = tid >> 2;
    const int lk = (tid & 3) << 2;

    for (int k0 = kBeg; k0 < kEnd; k0 += 16) {
        {
            int row = bm + lm;
            float va[4] = {0.f, 0.f, 0.f, 0.f};
            if (row < M) {
                size_t base = (size_t)(row / RD) * S1 + (size_t)(row % RD) * S2;
                int kg = k0 + lk;
#pragma unroll
                for (int i = 0; i < 4; i++)
                    if (kg + i < kEnd) va[i] = A[base + (size_t)(kg + i) * kstride];
            }
#pragma unroll
            for (int i = 0; i < 4; i++) As[lk + i][lm] = va[i];
        }
        {
            int col = bn + lm;
            float vb[4] = {0.f, 0.f, 0.f, 0.f};
            if (col < N) {
                int kg = k0 + lk;
#pragma unroll
                for (int i = 0; i < 4; i++)
                    if (kg + i < kEnd) vb[i] = W[(size_t)col * K + kg + i];
            }
#pragma unroll
            for (int i = 0; i < 4; i++) Bs[lk + i][lm] = vb[i];
        }
        __syncthreads();
#pragma unroll
        for (int k = 0; k < 16; k++) {
            float4 av = *(const float4*)&As[k][tm];
            float4 bv = *(const float4*)&Bs[k][tn];
            float a4[4] = {av.x, av.y, av.z, av.w};
            float b4[4] = {bv.x, bv.y, bv.z, bv.w};
#pragma unroll
            for (int i = 0; i < 4; i++)
#pragma unroll
                for (int j = 0; j < 4; j++) acc[i][j] += a4[i] * b4[j];
        }
        __syncthreads();
    }

    float* Cz = C + (size_t)blockIdx.z * M * N;
#pragma unroll
    for (int i = 0; i < 4; i++) {
        int row = bm + tm + i;
        if (row >= M) continue;
#pragma unroll
        for (int j = 0; j < 4; j++) {
            int col = bn + tn + j;
            if (col >= N) continue;
            float v = acc[i][j];
            if (blockIdx.z == 0) {
                if (bias1) v += bias1[col];
                if (bias2) v += bias2[col];
            }
            if (relu) v = fmaxf(v, 0.f);
            Cz[(size_t)row * N + col] = v;
        }
    }
}

// ---------------- fused LSTM step (GEMM + last-block gate epilogue) ----------------
__global__ __launch_bounds__(256) void lstm_fused(const float* __restrict__ W_hh, int t) {
    __shared__ float As[16][64];
    __shared__ float Bs[16][64];
    __shared__ int s_last;
    const int ct = blockIdx.x;
    const int z = blockIdx.y;
    const int bn = ct * 64;
    const int tid = threadIdx.x;
    const int tm = (tid / 16) * 4;
    const int tn = (tid % 16) * 4;

    float acc[4][4];
#pragma unroll
    for (int i = 0; i < 4; i++)
#pragma unroll
        for (int j = 0; j < 4; j++) acc[i][j] = 0.f;

    if (t > 0) {
        const float* hprev = g_hs + (size_t)(t - 1) * BB * HH;
        const int lm = tid >> 2;
        const int lk = (tid & 3) << 2;
        int kBeg = z * 256;
        for (int k0 = kBeg; k0 < kBeg + 256; k0 += 16) {
            {
                int kg = k0 + lk;
                float4 va = *(const float4*)&hprev[lm * HH + kg];
                As[lk + 0][lm] = va.x; As[lk + 1][lm] = va.y;
                As[lk + 2][lm] = va.z; As[lk + 3][lm] = va.w;
            }
            {
                int col = bn + lm;
                int r = (col & 3) * HH + (col >> 2);
                int kg = k0 + lk;
                float4 vb = *(const float4*)&W_hh[(size_t)r * HH + kg];
                Bs[lk + 0][lm] = vb.x; Bs[lk + 1][lm] = vb.y;
                Bs[lk + 2][lm] = vb.z; Bs[lk + 3][lm] = vb.w;
            }
            __syncthreads();
#pragma unroll
            for (int k = 0; k < 16; k++) {
                float4 av = *(const float4*)&As[k][tm];
                float4 bv = *(const float4*)&Bs[k][tn];
                float a4[4] = {av.x, av.y, av.z, av.w};
                float b4[4] = {bv.x, bv.y, bv.z, bv.w};
#pragma unroll
                for (int i = 0; i < 4; i++)
#pragma unroll
                    for (int j = 0; j < 4; j++) acc[i][j] += a4[i] * b4[j];
            }
            __syncthreads();
        }
    }

    float* Pz = g_gates + (size_t)z * BB * G4;
#pragma unroll
    for (int i = 0; i < 4; i++)
#pragma unroll
        for (int j = 0; j < 4; j++)
            Pz[(size_t)(tm + i) * G4 + bn + tn + j] = acc[i][j];

    __threadfence();
    __syncthreads();
    if (tid == 0) {
        int d = atomicAdd(&g_cnt[ct], 1);
        s_last = (d == 3) ? 1 : 0;
    }
    __syncthreads();
    if (!s_last) return;
    __threadfence();
    if (tid == 0) g_cnt[ct] = 0;

#pragma unroll
    for (int i = 0; i < 4; i++) {
        int idx = tid + 256 * i;
        int b = idx >> 4;
        int hl = idx & 15;
        int h = ct * 16 + hl;
        const float* xw = g_xW + (size_t)(t * BB + b) * G4;
        float gv[4];
#pragma unroll
        for (int g = 0; g < 4; g++) {
            int c = bn + hl * 4 + g;
            float s = __ldcg(&g_gates[(size_t)b * G4 + c])
                    + __ldcg(&g_gates[(size_t)(BB + b) * G4 + c])
                    + __ldcg(&g_gates[(size_t)(2 * BB + b) * G4 + c])
                    + __ldcg(&g_gates[(size_t)(3 * BB + b) * G4 + c]);
            gv[g] = s + xw[g * HH + h];
        }
        int id = b * HH + h;
        float cn = sigmoidf_(gv[1]) * g_c[id] + sigmoidf_(gv[0]) * tanhf(gv[2]);
        float hn = sigmoidf_(gv[3]) * tanhf(cn);
        g_c[id] = cn;
        g_hs[(size_t)t * BB * HH + id] = hn;
    }
}

// ---------------- 2-channel 1x1 conv (512 -> 2) ----------------
__global__ void att2_k(const float* __restrict__ X, const float* __restrict__ W2,
                       const float* __restrict__ b2, float* __restrict__ out,
                       int L, int bdiv) {
    int r = blockIdx.x;
    const float* a = X + (size_t)r * 512;
    float s0 = 0.f, s1 = 0.f;
    for (int o = threadIdx.x; o < 512; o += 128) {
        float v = a[o];
        s0 += W2[o] * v; s1 += W2[512 + o] * v;
    }
    __shared__ float r0[128], r1[128];
    r0[threadIdx.x] = s0; r1[threadIdx.x] = s1; __syncthreads();
    for (int st = 64; st > 0; st >>= 1) {
        if (threadIdx.x < st) { r0[threadIdx.x] += r0[threadIdx.x + st]; r1[threadIdx.x] += r1[threadIdx.x + st]; }
        __syncthreads();
    }
    if (threadIdx.x == 0) {
        int b, l;
        if (bdiv == 0) { b = r & 63; l = r >> 6; }
        else { b = r / 49; l = r % 49; }
        out[(b * 2 + 0) * L + l] = r0[0] + b2[0];
        out[(b * 2 + 1) * L + l] = r1[0] + b2[1];
    }
}

// ---------------- small row softmax (n <= 64), 64 threads ----------------
__global__ void softmax_small(const float* __restrict__ in, float* __restrict__ out, int n) {
    __shared__ float sm[64];
    int r = blockIdx.x, tid = threadIdx.x;
    float v = (tid < n) ? in[(size_t)r * n + tid] : -1e30f;
    sm[tid] = v; __syncthreads();
    for (int st = 32; st > 0; st >>= 1) {
        if (tid < st) sm[tid] = fmaxf(sm[tid], sm[tid + st]);
        __syncthreads();
    }
    float mx = sm[0]; __syncthreads();
    float e = (tid < n) ? expf(v - mx) : 0.f;
    sm[tid] = e; __syncthreads();
    for (int st = 32; st > 0; st >>= 1) {
        if (tid < st) sm[tid] += sm[tid + st];
        __syncthreads();
    }
    if (tid < n) out[(size_t)r * n + tid] = e / sm[0];
}

// ---------------- question feature + signed copies ----------------
__global__ void qfeat_k(const int* __restrict__ s1q, const int* __restrict__ s2q) {
    int b = blockIdx.x, g = blockIdx.y;
    __shared__ float att[TT];
    if (threadIdx.x < TT) att[threadIdx.x] = g_qatt[(b * 2 + g) * TT + threadIdx.x];
    __syncthreads();
    for (int h = threadIdx.x; h < HH; h += blockDim.x) {
        float acc = 0.f;
        for (int t = 0; t < TT; t++)
            acc += att[t] * g_hs[((size_t)t * BB + b) * HH + h];
        int j = g * HH + h;
        g_qfeat[b * QDIM + j] = acc;
        g_qv1[b * QDIM + j] = acc * (float)(2 * s1q[j] - 1);
        g_qv2[b * QDIM + j] = acc * (float)(2 * s2q[j] - 1);
    }
}

// ---------------- MCB1: scatter, pool ----------------
__global__ void scatter1(const float* __restrict__ img, const int* __restrict__ h1x,
                         const int* __restrict__ s1x) {
    int id = blockIdx.x * 256 + threadIdx.x;
    if (id >= BB * SS * FEATN) return;
    int f = id % FEATN;
    int r = id / FEATN;
    int s = r % SS, b = r / SS;
    int n = f * SS + s;
    float v = img[id] * (float)(2 * s1x[n] - 1);
    atomicAdd(&g_csx[(size_t)b * D1N + h1x[n]], v);
}

__global__ void pool1() {
    int id = blockIdx.x * 256 + threadIdx.x;
    if (id >= BB * D1N) return;
    int t = id % D1N; int b = id / D1N;
    const float* cs = g_csx + (size_t)b * D1N;
    float a = 0.f;
#pragma unroll
    for (int f = 0; f < 5; f++) {
        int tt = t + 49 * f;
        if (tt >= D1N) tt -= D1N;
        a += cs[tt];
    }
    g_P1[id] = a;
}

// ---------------- MCB1 conv: smem window over bins, j-quad inner ----------------
__global__ void conv1_k() {
    extern __shared__ float smw[];
    float* win = smw;                    // [WSZ]
    float* sq  = smw + WSZ;              // [JPAD]
    int*   sh  = (int*)(sq + JPAD);      // [JPAD]
    int b = blockIdx.y;
    int m0 = blockIdx.x * MTILE;
    int tid = threadIdx.x;

    for (int i = tid; i < JPAD; i += CTHREADS) {
        sq[i] = g_qp1[b * JPAD + i];
        sh[i] = g_hperm[i];
    }

    int mg = tid >> 6;
    int sl = tid & 63;
    bool lane_ok = sl < 49;
    int offb = 245 * mg + sl;
    float acc[7] = {0.f, 0.f, 0.f, 0.f, 0.f, 0.f, 0.f};
    const float* Pb = g_P1 + (size_t)b * D1N;
    int T0 = 245 * m0;

    for (int k = 0; k < NBINS; k++) {
        __syncthreads();
        int W0 = T0 - (k + 1) * BIN1 + 1;
        W0 %= D1N; if (W0 < 0) W0 += D1N;
        for (int i = tid; i < WSZ; i += CTHREADS) {
            int g = W0 + i; if (g >= D1N) g -= D1N;
            win[i] = Pb[g];
        }
        __syncthreads();
        int j0 = g_binoff[k], j1 = g_binoff[k + 1];
        if (lane_ok) {
            int base0 = (k + 1) * BIN1 - 1 + offb;
            for (int j = j0; j < j1; j += 4) {
                float4 q4 = *(const float4*)&sq[j];
                int4   h4 = *(const int4*)&sh[j];
                {
                    int a = base0 - h4.x; float q = q4.x;
#pragma unroll
                    for (int it = 0; it < 7; it++) acc[it] += q * win[a + 2450 * it];
                }
                {
                    int a = base0 - h4.y; float q = q4.y;
#pragma unroll
                    for (int it = 0; it < 7; it++) acc[it] += q * win[a + 2450 * it];
                }
                {
                    int a = base0 - h4.z; float q = q4.z;
#pragma unroll
                    for (int it = 0; it < 7; it++) acc[it] += q * win[a + 2450 * it];
                }
                {
                    int a = base0 - h4.w; float q = q4.w;
#pragma unroll
                    for (int it = 0; it < 7; it++) acc[it] += q * win[a + 2450 * it];
                }
            }
        }
    }

    if (lane_ok) {
#pragma unroll
        for (int it = 0; it < 7; it++) {
            int m = mg + 10 * it;
            if (m < MTILE && m0 + m < MON)
                g_iq[(size_t)b * IQN + (m0 + m) * 49 + sl] = acc[it];
        }
    }
}

__global__ void norm1_k() {
    int b = blockIdx.x, tid = threadIdx.x;
    __shared__ float red[256];
    float s = 0.f;
    const float* x = g_iq + (size_t)b * IQN;
    for (int i = tid; i < IQN; i += 256) s += fabsf(x[i]);
    red[tid] = s; __syncthreads();
    for (int st = 128; st > 0; st >>= 1) {
        if (tid < st) red[tid] += red[tid + st];
        __syncthreads();
    }
    if (tid == 0) g_nrm1[b] = 1.f / fmaxf(sqrtf(red[0]), 1e-12f);
}

__global__ void scale1_k() {
    int id = blockIdx.x * 256 + threadIdx.x;
    if (id >= BB * IQN) return;
    int b = id / IQN;
    float x = g_iq[id];
    g_iqn[id] = copysignf(sqrtf(fabsf(x)), x) * g_nrm1[b];
}

// ---------------- image feature ----------------
__global__ void ifeat_k(const float* __restrict__ img) {
    int b = blockIdx.x;
    __shared__ float a0[SS], a1[SS];
    if (threadIdx.x < SS) {
        a0[threadIdx.x] = g_iatt[(b * 2 + 0) * SS + threadIdx.x];
        a1[threadIdx.x] = g_iatt[(b * 2 + 1) * SS + threadIdx.x];
    }
    __syncthreads();
    int f = blockIdx.y * 256 + threadIdx.x;
    float acc0 = 0.f, acc1 = 0.f;
    for (int s = 0; s < SS; s++) {
        float v = img[((size_t)b * SS + s) * FEATN + f];
        acc0 += a0[s] * v; acc1 += a1[s] * v;
    }
    g_ifeat[b * IDIM + f] = acc0;
    g_ifeat[b * IDIM + FEATN + f] = acc1;
}

// ---------------- MCB2 fully fused ----------------
__global__ void mcb2_k(const int* __restrict__ h2i, const int* __restrict__ s2i,
                       const int* __restrict__ h2q) {
    __shared__ float cs[D2N];
    __shared__ float sq[QDIM];
    __shared__ int   shh[QDIM];
    __shared__ float red[256];
    int b = blockIdx.x, tid = threadIdx.x;
    for (int i = tid; i < D2N; i += 256) cs[i] = 0.f;
    for (int j = tid; j < QDIM; j += 256) { sq[j] = g_qv2[b * QDIM + j]; shh[j] = h2q[j]; }
    __syncthreads();
    for (int n = tid; n < IDIM; n += 256) {
        float v = g_ifeat[b * IDIM + n] * (float)(2 * s2i[n] - 1);
        atomicAdd(&cs[h2i[n]], v);
    }
    __syncthreads();
    float p[20];
#pragma unroll
    for (int k = 0; k < 20; k++) {
        int t = tid + k * 256;
        float a = 0.f;
        if (t < D2N) {
#pragma unroll
            for (int f = 0; f < 5; f++) { int u = t + f; if (u >= D2N) u -= D2N; a += cs[u]; }
        }
        p[k] = a;
    }
    __syncthreads();
#pragma unroll
    for (int k = 0; k < 20; k++) { int t = tid + k * 256; if (t < D2N) cs[t] = p[k]; }
    __syncthreads();
    float z[4] = {0.f, 0.f, 0.f, 0.f};
    int mb[4];
#pragma unroll
    for (int k = 0; k < 4; k++) { int m = tid + k * 256; mb[k] = (m < MON) ? 5 * m : 0; }
    for (int j = 0; j < QDIM; j++) {
        int h = shh[j]; float q = sq[j];
#pragma unroll
        for (int k = 0; k < 4; k++) { int d = mb[k] - h; if (d < 0) d += D2N; z[k] += q * cs[d]; }
    }
    float sa = 0.f;
#pragma unroll
    for (int k = 0; k < 4; k++) { if (tid + k * 256 < MON) sa += fabsf(z[k]); }
    red[tid] = sa; __syncthreads();
    for (int st = 128; st > 0; st >>= 1) {
        if (tid < st) red[tid] += red[tid + st];
        __syncthreads();
    }
    float inv = 1.f / fmaxf(sqrtf(red[0]), 1e-12f);
#pragma unroll
    for (int k = 0; k < 4; k++) {
        int m = tid + k * 256;
        if (m < MON) g_z2n[b * MON + m] = copysignf(sqrtf(fabsf(z[k])), z[k]) * inv;
    }
}

// ---------------- final softmax (3000) ----------------
__global__ void softmax_out(float* __restrict__ out) {
    int b = blockIdx.x, tid = threadIdx.x;
    __shared__ float red[256];
    const float* lg = g_logits + (size_t)b * VOCABN;
    float mx = -1e30f;
    for (int i = tid; i < VOCABN; i += 256) mx = fmaxf(mx, lg[i]);
    red[tid] = mx; __syncthreads();
    for (int st = 128; st > 0; st >>= 1) {
        if (tid < st) red[tid] = fmaxf(red[tid], red[tid + st]);
        __syncthreads();
    }
    mx = red[0]; __syncthreads();
    float s = 0.f;
    for (int i = tid; i < VOCABN; i += 256) s += expf(lg[i] - mx);
    red[tid] = s; __syncthreads();
    for (int st = 128; st > 0; st >>= 1) {
        if (tid < st) red[tid] += red[tid + st];
        __syncthreads();
    }
    float inv = 1.f / red[0];
    for (int i = tid; i < VOCABN; i += 256) out[(size_t)b * VOCABN + i] = expf(lg[i] - mx) * inv;
}

// ---------------- host launcher ----------------
static float* sym(const void* s) {
    void* p = nullptr;
    cudaGetSymbolAddress(&p, s);
    return (float*)p;
}

extern "C" void kernel_launch(void* const* d_in, const int* in_sizes, int n_in,
                              void* d_out, int out_size) {
    const float* ques  = (const float*)d_in[0];
    const float* img   = (const float*)d_in[1];
    const float* W_ih  = (const float*)d_in[2];
    const float* W_hh  = (const float*)d_in[3];
    const float* b_ih  = (const float*)d_in[4];
    const float* b_hh  = (const float*)d_in[5];
    const float* Wq1   = (const float*)d_in[6];
    const float* bq1   = (const float*)d_in[7];
    const float* Wq2   = (const float*)d_in[8];
    const float* bq2   = (const float*)d_in[9];
    const float* Wi1   = (const float*)d_in[10];
    const float* bi1   = (const float*)d_in[11];
    const float* Wi2   = (const float*)d_in[12];
    const float* bi2   = (const float*)d_in[13];
    const float* Wp    = (const float*)d_in[14];
    const float* bp    = (const float*)d_in[15];
    const int* h1x = (const int*)d_in[16];
    const int* s1x = (const int*)d_in[17];
    const int* h1q = (const int*)d_in[18];
    const int* s1q = (const int*)d_in[19];
    const int* h2i = (const int*)d_in[20];
    const int* s2i = (const int*)d_in[21];
    const int* h2q = (const int*)d_in[22];
    const int* s2q = (const int*)d_in[23];
    float* out = (float*)d_out;

    float* p_xW    = sym(g_xW);
    float* p_hs    = sym(g_hs);
    float* p_qa1   = sym(g_qa1);
    float* p_qa2   = sym(g_qa2);
    float* p_qatt  = sym(g_qatt);
    float* p_ia1   = sym(g_ia1);
    float* p_ia2   = sym(g_ia2);
    float* p_iatt  = sym(g_iatt);
    float* p_iqn   = sym(g_iqn);
    float* p_z2n   = sym(g_z2n);
    float* p_logits= sym(g_logits);

    cudaFuncSetAttribute(conv1_k, cudaFuncAttributeMaxDynamicSharedMemorySize, CONV_SMEM);

    // side stream + events for overlapping img-side preprocessing with LSTM.
    // Created fresh per call (kernel_launch is invoked only a handful of times;
    // the timed loop replays the captured graph). Never destroyed: destroying
    // during capture is illegal.
    cudaStream_t side;
    cudaStreamCreateWithFlags(&side, cudaStreamNonBlocking);
    cudaEvent_t e_fork, e_join;
    cudaEventCreateWithFlags(&e_fork, cudaEventDisableTiming);
    cudaEventCreateWithFlags(&e_join, cudaEventDisableTiming);

    // main-stream init needed by both branches
    init_state_k<<<(BB*HH + 255)/256, 256>>>();
    bin_h_k<<<1, 256>>>(h1q);

    // fork: img-side preprocessing on side stream
    cudaEventRecord(e_fork, 0);
    cudaStreamWaitEvent(side, e_fork, 0);
    zero_csx_k<<<(BB*D1N + 255)/256, 256, 0, side>>>();
    scatter1<<<(BB*SS*FEATN + 255)/256, 256, 0, side>>>(img, h1x, s1x);
    pool1<<<(BB*D1N + 255)/256, 256, 0, side>>>();
    cudaEventRecord(e_join, side);

    // main stream: xW GEMM + LSTM chain
    {
        dim3 g(G4/64, (TT*BB + 63)/64, 1);
        sgemm<<<g, 256>>>(ques, W_ih, b_ih, b_hh, p_xW,
                          TT*BB, G4, EE, BB, EE, TT*EE, 1, 0);
    }
    for (int t = 0; t < TT; t++) {
        dim3 g(64, 4, 1);
        lstm_fused<<<g, 256>>>(W_hh, t);
    }

    // question attention
    {
        dim3 g(512/64, (TT*BB + 63)/64, 1);
        sgemm<<<g, 256>>>(p_hs, Wq1, bq1, nullptr, p_qa1,
                          TT*BB, 512, HH, 1, HH, 0, 1, 1);
    }
    att2_k<<<TT*BB, 128>>>(p_qa1, Wq2, bq2, p_qa2, TT, 0);
    softmax_small<<<BB*2, 64>>>(p_qa2, p_qatt, TT);
    {
        dim3 g(BB, 2);
        qfeat_k<<<g, 256>>>(s1q, s2q);
    }
    permq_k<<<BB, 256>>>();

    // join: conv1 needs pool1 (side) + permq (main)
    cudaStreamWaitEvent(0, e_join, 0);

    // MCB1 conv + normalize
    {
        dim3 g((MON + MTILE - 1)/MTILE, BB);
        conv1_k<<<g, CTHREADS, CONV_SMEM>>>();
    }
    norm1_k<<<BB, 256>>>();
    scale1_k<<<(BB*IQN + 255)/256, 256>>>();

    // image attention
    {
        dim3 g(512/64, (BB*SS + 63)/64, 1);
        sgemm<<<g, 256>>>(p_iqn, Wi1, bi1, nullptr, p_ia1,
                          BB*SS, 512, MON, SS, IQN, 1, SS, 1);
    }
    att2_k<<<BB*SS, 128>>>(p_ia1, Wi2, bi2, p_ia2, SS, 1);
    softmax_small<<<BB*2, 64>>>(p_ia2, p_iatt, SS);
    {
        dim3 g(BB, FEATN/256);
        ifeat_k<<<g, 256>>>(img);
    }

    // MCB2 fused
    mcb2_k<<<BB, 256>>>(h2i, s2i, h2q);

    // classifier + softmax
    {
        dim3 g((VOCABN + 63)/64, 1, 1);
        sgemm<<<g, 256>>>(p_z2n, Wp, bp, nullptr, p_logits,
                          BB, VOCABN, MON, 1, MON, 0, 1, 0);
    }
    softmax_out<<<BB, 256>>>(out);
}